// round 4
// baseline (speedup 1.0000x reference)
#include <cuda_runtime.h>
#include <cuda_bf16.h>
#include <cstdint>

// ---------------- problem constants ----------------
#define N_NODES 50000
#define N_EDGES 1600000
#define E_TOT   (N_EDGES + N_NODES)   // + self loops
#define F_IN    128

#define SCAN_B   256
#define SCAN_NB  ((N_NODES + SCAN_B - 1) / SCAN_B)   // 196

// ---------------- device scratch ----------------
__device__ float g_h[(size_t)N_NODES * 384];    // h (layers1/2) / aggx (layer3)
__device__ float g_agg[(size_t)N_NODES * 64];   // aggregated output (layers 1,2)
__device__ float g_als[(size_t)N_NODES * 6];
__device__ float g_ald[(size_t)N_NODES * 6];
__device__ float g_wbuf[(size_t)E_TOT * 6];     // per-CSR-slot exp(e) values
__device__ float g_w3cat[384 * 40];             // folded W3 (head-mean included)
__device__ float g_bs[64 * 6];                  // W3 @ a3s per head
__device__ float g_bd[64 * 6];                  // W3 @ a3d per head
__device__ int   g_counts[N_NODES];
__device__ int   g_cursor[N_NODES];
__device__ int   g_offsets[N_NODES + 1];
__device__ int   g_csr[E_TOT];
__device__ int   g_bsum[SCAN_NB];
__device__ int   g_bpre[SCAN_NB];
__device__ int   g_idx64;

// ---------------- dtype detect ----------------
__global__ void detect_idx_kernel(const int* p) {
    int lane = threadIdx.x;
    int bad = 0;
    #pragma unroll
    for (int r = 0; r < 8; r++) {
        int i = lane + r * 32;
        if (p[2 * i + 1] != 0) bad = 1;
    }
    bad = __any_sync(0xffffffffu, bad);
    if (lane == 0) g_idx64 = bad ? 0 : 1;
}

__device__ __forceinline__ void load_edge(const void* ei, int i, int& src, int& dst) {
    if (i < N_EDGES) {
        if (g_idx64) {
            const long long* q = (const long long*)ei;
            src = (int)q[i];
            dst = (int)q[(size_t)N_EDGES + i];
        } else {
            const int* q = (const int*)ei;
            src = q[i];
            dst = q[N_EDGES + i];
        }
    } else {
        src = dst = i - N_EDGES;  // self loop
    }
}

__global__ void count_kernel(const void* ei) {
    int i = blockIdx.x * blockDim.x + threadIdx.x;
    if (i >= E_TOT) return;
    int src, dst;
    load_edge(ei, i, src, dst);
    atomicAdd(&g_counts[dst], 1);
}

// ---------------- 3-stage parallel exclusive scan ----------------
__global__ void bsum_kernel() {
    int b = blockIdx.x, t = threadIdx.x;
    int idx = b * SCAN_B + t;
    int v = (idx < N_NODES) ? g_counts[idx] : 0;
    #pragma unroll
    for (int o = 16; o > 0; o >>= 1) v += __shfl_xor_sync(0xffffffffu, v, o);
    __shared__ int ws[SCAN_B / 32];
    if ((t & 31) == 0) ws[t >> 5] = v;
    __syncthreads();
    if (t < SCAN_B / 32) {
        int s = ws[t];
        #pragma unroll
        for (int o = SCAN_B / 64; o > 0; o >>= 1) s += __shfl_xor_sync(0xffu, s, o);
        if (t == 0) g_bsum[b] = s;
    }
}

__global__ void bscan_kernel() {
    __shared__ int sm[SCAN_B];
    int t = threadIdx.x;
    int v = (t < SCAN_NB) ? g_bsum[t] : 0;
    sm[t] = v;
    __syncthreads();
    #pragma unroll
    for (int off = 1; off < SCAN_B; off <<= 1) {
        int u = (t >= off) ? sm[t - off] : 0;
        __syncthreads();
        sm[t] += u;
        __syncthreads();
    }
    if (t < SCAN_NB) g_bpre[t] = sm[t] - v;
}

__global__ void offsets_kernel() {
    __shared__ int sm[SCAN_B];
    int b = blockIdx.x, t = threadIdx.x;
    int idx = b * SCAN_B + t;
    int v = (idx < N_NODES) ? g_counts[idx] : 0;
    sm[t] = v;
    __syncthreads();
    #pragma unroll
    for (int off = 1; off < SCAN_B; off <<= 1) {
        int u = (t >= off) ? sm[t - off] : 0;
        __syncthreads();
        sm[t] += u;
        __syncthreads();
    }
    int excl = sm[t] - v + g_bpre[b];
    if (idx < N_NODES) {
        g_offsets[idx] = excl;
        g_cursor[idx] = excl;
    }
    if (idx == 0) g_offsets[N_NODES] = E_TOT;
}

__global__ void fill_kernel(const void* ei) {
    int i = blockIdx.x * blockDim.x + threadIdx.x;
    if (i >= E_TOT) return;
    int src, dst;
    load_edge(ei, i, src, dst);
    int pos = atomicAdd(&g_cursor[dst], 1);
    g_csr[pos] = src;
}

// ---------------- layer-3 prep: fold attention vecs and head-mean into W3 ----------------
// Bs[k,h] = sum_c W3[k, h*40+c] * a3s[h,c]     (same for Bd)
__global__ void prep3_kernel(const float* __restrict__ W3, const float* __restrict__ a3s,
                             const float* __restrict__ a3d) {
    int t = blockIdx.x * blockDim.x + threadIdx.x;
    if (t >= 384) return;
    int k = t / 6, h = t % 6;
    float ss = 0.f, sd = 0.f;
    #pragma unroll
    for (int c = 0; c < 40; c++) {
        float w = W3[k * 240 + h * 40 + c];
        ss += w * a3s[h * 40 + c];
        sd += w * a3d[h * 40 + c];
    }
    g_bs[k * 6 + h] = ss;
    g_bd[k * 6 + h] = sd;
}

// Wcat[h*64+k, c] = W3[k, h*40+c] / 6   (head-mean folded)
__global__ void prep_wcat_kernel(const float* __restrict__ W3) {
    int i = blockIdx.x * blockDim.x + threadIdx.x;
    if (i >= 384 * 40) return;
    int hk = i / 40, c = i % 40;
    int h = hk >> 6, k = hk & 63;
    g_w3cat[i] = W3[k * 240 + h * 40 + c] * (1.f / 6.f);
}

// als/ald[n, 0..5] = x[n,:] @ Bs / Bd  (tiny GEMM, 64 nodes per block)
__global__ void logit3_kernel(const float* __restrict__ X) {
    __shared__ float xs[64 * 65];
    __shared__ float Bsm[64 * 12];
    int tid = threadIdx.x;
    int n0 = blockIdx.x * 64;
    for (int i = tid; i < 768; i += 256) {
        int k = i / 12, j = i % 12;
        Bsm[k * 12 + j] = (j < 6) ? g_bs[k * 6 + j] : g_bd[k * 6 + (j - 6)];
    }
    for (int i = tid; i < 64 * 64; i += 256) {
        int m = i >> 6, k = i & 63;
        int gm = n0 + m;
        xs[m * 65 + k] = (gm < N_NODES) ? X[(size_t)gm * 64 + k] : 0.f;
    }
    __syncthreads();
    for (int p = tid; p < 768; p += 256) {
        int m = p / 12, j = p % 12;
        float s = 0.f;
        #pragma unroll
        for (int k = 0; k < 64; k++) s = fmaf(xs[m * 65 + k], Bsm[k * 12 + j], s);
        int gm = n0 + m;
        if (gm < N_NODES) {
            if (j < 6) g_als[gm * 6 + j] = s;
            else       g_ald[gm * 6 + (j - 6)] = s;
        }
    }
}

// ---------------- fused GEMM + attention-logit kernel (layers 1,2) ----------------
template <int K, int F, int BM, int TM, int TF, int H>
__global__ void gemm_al_kernel(const float* __restrict__ X, const float* __restrict__ W,
                               const float* __restrict__ Avs, const float* __restrict__ Avd,
                               float* __restrict__ Ho, float* __restrict__ als,
                               float* __restrict__ ald, int Nn) {
    constexpr int MTH = BM / TM;
    constexpr int FTH = F / TF;
    constexpr int NTH = MTH * FTH;
    constexpr int C = F / H;
    constexpr int XLD = K + 1;
    extern __shared__ float sh[];
    float* ws = sh;
    float* xs = ws + K * F;
    float* asum = xs + BM * XLD;

    int tid = threadIdx.x;
    for (int i = tid; i < K * F; i += NTH) ws[i] = W[i];

    int mx = tid % MTH;
    int fx = tid / MTH;
    int f0 = fx * TF;
    int headT = f0 / C;
    float ras[TF], rad[TF];
    #pragma unroll
    for (int j = 0; j < TF; j++) { ras[j] = Avs[f0 + j]; rad[j] = Avd[f0 + j]; }

    for (int tile = blockIdx.x * BM; tile < Nn; tile += gridDim.x * BM) {
        __syncthreads();
        for (int i = tid; i < BM * K; i += NTH) {
            int m = i / K, k = i - m * K;
            int gm = tile + m;
            xs[m * XLD + k] = (gm < Nn) ? X[(size_t)gm * K + k] : 0.f;
        }
        for (int i = tid; i < BM * 2 * H; i += NTH) asum[i] = 0.f;
        __syncthreads();

        float acc[TM][TF];
        #pragma unroll
        for (int i = 0; i < TM; i++)
            #pragma unroll
            for (int j = 0; j < TF; j++) acc[i][j] = 0.f;

        #pragma unroll 4
        for (int k = 0; k < K; k++) {
            float xv[TM];
            #pragma unroll
            for (int i = 0; i < TM; i++) xv[i] = xs[(mx + i * MTH) * XLD + k];
            float wv[TF];
            #pragma unroll
            for (int j4 = 0; j4 < TF / 4; j4++) {
                float4 w4 = *reinterpret_cast<const float4*>(&ws[k * F + f0 + j4 * 4]);
                wv[j4 * 4 + 0] = w4.x; wv[j4 * 4 + 1] = w4.y;
                wv[j4 * 4 + 2] = w4.z; wv[j4 * 4 + 3] = w4.w;
            }
            #pragma unroll
            for (int i = 0; i < TM; i++)
                #pragma unroll
                for (int j = 0; j < TF; j++) acc[i][j] = fmaf(xv[i], wv[j], acc[i][j]);
        }

        #pragma unroll
        for (int i = 0; i < TM; i++) {
            int m = mx + i * MTH;
            int gm = tile + m;
            if (gm < Nn) {
                float ss = 0.f, sd = 0.f;
                #pragma unroll
                for (int j = 0; j < TF; j++) {
                    Ho[(size_t)gm * F + f0 + j] = acc[i][j];
                    ss += acc[i][j] * ras[j];
                    sd += acc[i][j] * rad[j];
                }
                atomicAdd(&asum[m * 2 * H + headT], ss);
                atomicAdd(&asum[m * 2 * H + H + headT], sd);
            }
        }
        __syncthreads();
        for (int i = tid; i < BM * H; i += NTH) {
            int m = i / H, hh = i - m * H;
            int gm = tile + m;
            if (gm < Nn) {
                als[gm * H + hh] = asum[m * 2 * H + hh];
                ald[gm * H + hh] = asum[m * 2 * H + H + hh];
            }
        }
    }
}

// ---------------- per-dst softmax aggregation, layers 1/2 (H=4, F=64) ----------------
__global__ void agg12_kernel(const float* __restrict__ h, const float* __restrict__ als,
                             const float* __restrict__ ald, const float* __restrict__ bias,
                             float* __restrict__ out, float* __restrict__ wbuf) {
    int gw = (blockIdx.x * blockDim.x + threadIdx.x) >> 5;
    if (gw >= N_NODES) return;
    int lane = threadIdx.x & 31;
    int beg = g_offsets[gw], end = g_offsets[gw + 1];

    float4 at = *reinterpret_cast<const float4*>(&ald[gw * 4]);
    float aldh[4] = {at.x, at.y, at.z, at.w};

    // pass 1: exp(leakyrelu(logit)) per edge per head; row sums
    float sv[4] = {0.f, 0.f, 0.f, 0.f};
    for (int i = beg + lane; i < end; i += 32) {
        int s = g_csr[i];
        float4 t = *reinterpret_cast<const float4*>(&als[s * 4]);
        float av[4] = {t.x, t.y, t.z, t.w};
        float w[4];
        #pragma unroll
        for (int hh = 0; hh < 4; hh++) {
            float e = av[hh] + aldh[hh];
            e = e > 0.f ? e : 0.2f * e;
            float x = __expf(e);
            w[hh] = x;
            sv[hh] += x;
        }
        *reinterpret_cast<float4*>(&wbuf[(size_t)i * 4]) =
            make_float4(w[0], w[1], w[2], w[3]);
    }
    #pragma unroll
    for (int hh = 0; hh < 4; hh++)
        #pragma unroll
        for (int o = 16; o > 0; o >>= 1)
            sv[hh] += __shfl_xor_sync(0xffffffffu, sv[hh], o);

    int ch = lane * 2;
    int hr = ch >> 4;  // C=16
    float inv = 1.f / sv[hr];

    // pass 2: raw-weight gather; normalize at the end
    float2 acc = make_float2(0.f, 0.f);
    #pragma unroll 2
    for (int i = beg; i < end; i++) {
        int s = g_csr[i];
        float wv = __ldg(&wbuf[(size_t)i * 4 + hr]);
        float2 hv = *reinterpret_cast<const float2*>(&h[(size_t)s * 64 + ch]);
        acc.x = fmaf(wv, hv.x, acc.x);
        acc.y = fmaf(wv, hv.y, acc.y);
    }

    float vx = acc.x * inv + bias[ch];
    float vy = acc.y * inv + bias[ch + 1];
    vx = vx > 0.f ? vx : (__expf(vx) - 1.f);
    vy = vy > 0.f ? vy : (__expf(vy) - 1.f);
    *reinterpret_cast<float2*>(&out[(size_t)gw * 64 + ch]) = make_float2(vx, vy);
}

// ---------------- layer-3 aggregation in input space (H=6, 64-dim x) ----------------
// aggx[d, h*64+k] = (1/sum) * sum_e expw_e^h * x[src_e, k]
__global__ void agg3x_kernel(const float* __restrict__ x, const float* __restrict__ als,
                             const float* __restrict__ ald, float* __restrict__ aggx,
                             float* __restrict__ wbuf) {
    int gw = (blockIdx.x * blockDim.x + threadIdx.x) >> 5;
    if (gw >= N_NODES) return;
    int lane = threadIdx.x & 31;
    int beg = g_offsets[gw], end = g_offsets[gw + 1];

    float aldh[6];
    #pragma unroll
    for (int q = 0; q < 3; q++) {
        float2 t = *reinterpret_cast<const float2*>(&ald[gw * 6 + 2 * q]);
        aldh[2 * q] = t.x; aldh[2 * q + 1] = t.y;
    }

    float sv[6] = {0.f, 0.f, 0.f, 0.f, 0.f, 0.f};
    for (int i = beg + lane; i < end; i += 32) {
        int s = g_csr[i];
        float av[6];
        #pragma unroll
        for (int q = 0; q < 3; q++) {
            float2 t = *reinterpret_cast<const float2*>(&als[s * 6 + 2 * q]);
            av[2 * q] = t.x; av[2 * q + 1] = t.y;
        }
        float w[6];
        #pragma unroll
        for (int hh = 0; hh < 6; hh++) {
            float e = av[hh] + aldh[hh];
            e = e > 0.f ? e : 0.2f * e;
            float xv = __expf(e);
            w[hh] = xv;
            sv[hh] += xv;
        }
        #pragma unroll
        for (int q = 0; q < 3; q++)
            *reinterpret_cast<float2*>(&wbuf[(size_t)i * 6 + 2 * q]) =
                make_float2(w[2 * q], w[2 * q + 1]);
    }
    #pragma unroll
    for (int hh = 0; hh < 6; hh++)
        #pragma unroll
        for (int o = 16; o > 0; o >>= 1)
            sv[hh] += __shfl_xor_sync(0xffffffffu, sv[hh], o);

    int ch = lane * 2;
    float2 acc[6];
    #pragma unroll
    for (int hh = 0; hh < 6; hh++) acc[hh] = make_float2(0.f, 0.f);

    for (int i = beg; i < end; i++) {
        int s = g_csr[i];
        float2 w01 = *reinterpret_cast<const float2*>(&wbuf[(size_t)i * 6 + 0]);
        float2 w23 = *reinterpret_cast<const float2*>(&wbuf[(size_t)i * 6 + 2]);
        float2 w45 = *reinterpret_cast<const float2*>(&wbuf[(size_t)i * 6 + 4]);
        float2 hv = *reinterpret_cast<const float2*>(&x[(size_t)s * 64 + ch]);
        acc[0].x = fmaf(w01.x, hv.x, acc[0].x); acc[0].y = fmaf(w01.x, hv.y, acc[0].y);
        acc[1].x = fmaf(w01.y, hv.x, acc[1].x); acc[1].y = fmaf(w01.y, hv.y, acc[1].y);
        acc[2].x = fmaf(w23.x, hv.x, acc[2].x); acc[2].y = fmaf(w23.x, hv.y, acc[2].y);
        acc[3].x = fmaf(w23.y, hv.x, acc[3].x); acc[3].y = fmaf(w23.y, hv.y, acc[3].y);
        acc[4].x = fmaf(w45.x, hv.x, acc[4].x); acc[4].y = fmaf(w45.x, hv.y, acc[4].y);
        acc[5].x = fmaf(w45.y, hv.x, acc[5].x); acc[5].y = fmaf(w45.y, hv.y, acc[5].y);
    }

    size_t base = (size_t)gw * 384;
    #pragma unroll
    for (int hh = 0; hh < 6; hh++) {
        float inv = 1.f / sv[hh];
        *reinterpret_cast<float2*>(&aggx[base + hh * 64 + ch]) =
            make_float2(acc[hh].x * inv, acc[hh].y * inv);
    }
}

// ---------------- final GEMM: [N,384] @ Wcat[384,40] + bias + elu + log_softmax ----------------
__global__ void gemm_final_kernel(const float* __restrict__ X, const float* __restrict__ b3,
                                  float* __restrict__ out, int Nn) {
    constexpr int BM = 128, BK = 64, Ktot = 384, F = 40;
    constexpr int TM = 8, TF = 5, MTH = 16, NTH = 128;  // FTH = 8
    extern __shared__ float sh[];
    float* ws = sh;              // 384*40
    float* xs = ws + Ktot * F;   // BM*(BK+1)

    int tid = threadIdx.x;
    for (int i = tid; i < Ktot * F; i += NTH) ws[i] = g_w3cat[i];

    int mx = tid % MTH;
    int fx = tid / MTH;
    int f0 = fx * TF;
    int tile = blockIdx.x * BM;

    float acc[TM][TF];
    #pragma unroll
    for (int i = 0; i < TM; i++)
        #pragma unroll
        for (int j = 0; j < TF; j++) acc[i][j] = 0.f;

    for (int kt = 0; kt < Ktot; kt += BK) {
        __syncthreads();
        for (int i = tid; i < BM * BK; i += NTH) {
            int m = i / BK, k = i - m * BK;
            int gm = tile + m;
            xs[m * (BK + 1) + k] = (gm < Nn) ? X[(size_t)gm * Ktot + kt + k] : 0.f;
        }
        __syncthreads();
        #pragma unroll 4
        for (int k = 0; k < BK; k++) {
            float xv[TM];
            #pragma unroll
            for (int i = 0; i < TM; i++) xv[i] = xs[(mx + i * MTH) * (BK + 1) + k];
            float wv[TF];
            #pragma unroll
            for (int j = 0; j < TF; j++) wv[j] = ws[(kt + k) * F + f0 + j];
            #pragma unroll
            for (int i = 0; i < TM; i++)
                #pragma unroll
                for (int j = 0; j < TF; j++) acc[i][j] = fmaf(xv[i], wv[j], acc[i][j]);
        }
    }

    // epilogue: bias + elu + per-row log_softmax
    __syncthreads();
    float* sbuf = xs;              // BM*40
    float* lrow = xs + BM * F;     // BM
    #pragma unroll
    for (int i = 0; i < TM; i++) {
        int m = mx + i * MTH;
        #pragma unroll
        for (int j = 0; j < TF; j++)
            sbuf[m * F + f0 + j] = acc[i][j] + b3[f0 + j];
    }
    __syncthreads();
    {
        int m = tid;  // 128 threads <-> 128 rows
        float mxv = -1e30f;
        #pragma unroll 4
        for (int c = 0; c < F; c++) {
            float v = sbuf[m * F + c];
            v = v > 0.f ? v : (__expf(v) - 1.f);
            sbuf[m * F + c] = v;
            mxv = fmaxf(mxv, v);
        }
        float se = 0.f;
        #pragma unroll 4
        for (int c = 0; c < F; c++) se += __expf(sbuf[m * F + c] - mxv);
        lrow[m] = __logf(se) + mxv;
    }
    __syncthreads();
    for (int i = tid; i < BM * F; i += NTH) {
        int m = i / F;
        int gm = tile + m;
        if (gm < Nn) out[(size_t)gm * F + (i - m * F)] = sbuf[i] - lrow[m];
    }
}

// ---------------- host launcher ----------------
extern "C" void kernel_launch(void* const* d_in, const int* in_sizes, int n_in,
                              void* d_out, int out_size) {
    const float* x   = (const float*)d_in[0];
    const void*  ei  = d_in[1];
    const float* W1  = (const float*)d_in[2];
    const float* a1s = (const float*)d_in[3];
    const float* a1d = (const float*)d_in[4];
    const float* b1  = (const float*)d_in[5];
    const float* W2  = (const float*)d_in[6];
    const float* a2s = (const float*)d_in[7];
    const float* a2d = (const float*)d_in[8];
    const float* b2  = (const float*)d_in[9];
    const float* W3  = (const float*)d_in[10];
    const float* a3s = (const float*)d_in[11];
    const float* a3d = (const float*)d_in[12];
    const float* b3  = (const float*)d_in[13];
    float* out = (float*)d_out;

    float *p_h, *p_agg, *p_als, *p_ald, *p_wbuf;
    int *p_counts;
    cudaGetSymbolAddress((void**)&p_h, g_h);
    cudaGetSymbolAddress((void**)&p_agg, g_agg);
    cudaGetSymbolAddress((void**)&p_als, g_als);
    cudaGetSymbolAddress((void**)&p_ald, g_ald);
    cudaGetSymbolAddress((void**)&p_wbuf, g_wbuf);
    cudaGetSymbolAddress((void**)&p_counts, g_counts);

    // ---- CSR build + layer-3 weight folding (independent work up front) ----
    detect_idx_kernel<<<1, 32>>>((const int*)ei);
    cudaMemsetAsync(p_counts, 0, N_NODES * sizeof(int));
    prep3_kernel<<<2, 256>>>(W3, a3s, a3d);
    prep_wcat_kernel<<<(384 * 40 + 255) / 256, 256>>>(W3);
    count_kernel<<<(E_TOT + 255) / 256, 256>>>(ei);
    bsum_kernel<<<SCAN_NB, SCAN_B>>>();
    bscan_kernel<<<1, SCAN_B>>>();
    offsets_kernel<<<SCAN_NB, SCAN_B>>>();
    fill_kernel<<<(E_TOT + 255) / 256, 256>>>(ei);

    const int AGG_GRID = (N_NODES * 32 + 255) / 256;

    // ---- layer 1: 128 -> 4x16 concat ----
    {
        constexpr int K = 128, F = 64, BM = 128, TM = 8, TF = 8, H = 4;
        size_t smem = (size_t)(K * F + BM * (K + 1) + BM * 2 * H) * sizeof(float);
        cudaFuncSetAttribute(gemm_al_kernel<K, F, BM, TM, TF, H>,
                             cudaFuncAttributeMaxDynamicSharedMemorySize, (int)smem);
        int grid = (N_NODES + BM - 1) / BM;
        gemm_al_kernel<K, F, BM, TM, TF, H><<<grid, (BM / TM) * (F / TF), smem>>>(
            x, W1, a1s, a1d, p_h, p_als, p_ald, N_NODES);
        agg12_kernel<<<AGG_GRID, 256>>>(p_h, p_als, p_ald, b1, p_agg, p_wbuf);
    }

    // ---- layer 2: 64 -> 4x16 concat ----
    {
        constexpr int K = 64, F = 64, BM = 128, TM = 8, TF = 8, H = 4;
        size_t smem = (size_t)(K * F + BM * (K + 1) + BM * 2 * H) * sizeof(float);
        cudaFuncSetAttribute(gemm_al_kernel<K, F, BM, TM, TF, H>,
                             cudaFuncAttributeMaxDynamicSharedMemorySize, (int)smem);
        int grid = (N_NODES + BM - 1) / BM;
        gemm_al_kernel<K, F, BM, TM, TF, H><<<grid, (BM / TM) * (F / TF), smem>>>(
            p_agg, W2, a2s, a2d, p_h, p_als, p_ald, N_NODES);
        agg12_kernel<<<AGG_GRID, 256>>>(p_h, p_als, p_ald, b2, p_agg, p_wbuf);
    }

    // ---- layer 3: logits from x, aggregate x per head, folded GEMM + softmax ----
    logit3_kernel<<<(N_NODES + 63) / 64, 256>>>(p_agg);
    agg3x_kernel<<<AGG_GRID, 256>>>(p_agg, p_als, p_ald, p_h, p_wbuf);
    {
        size_t smem = (size_t)(384 * 40 + 128 * 65) * sizeof(float);
        cudaFuncSetAttribute(gemm_final_kernel,
                             cudaFuncAttributeMaxDynamicSharedMemorySize, (int)smem);
        gemm_final_kernel<<<(N_NODES + 127) / 128, 128, smem>>>(p_h, b3, out, N_NODES);
    }
}

// round 5
// speedup vs baseline: 1.0647x; 1.0647x over previous
#include <cuda_runtime.h>
#include <cuda_bf16.h>
#include <cstdint>

// ---------------- problem constants ----------------
#define N_NODES 50000
#define N_EDGES 1600000
#define E_TOT   (N_EDGES + N_NODES)   // + self loops
#define F_IN    128

#define SCAN_B   256
#define SCAN_NB  ((N_NODES + SCAN_B - 1) / SCAN_B)   // 196

// ---------------- device scratch ----------------
__device__ float g_h[(size_t)N_NODES * 384];    // h (layers1/2) / aggx (layer3)
__device__ float g_agg[(size_t)N_NODES * 64];   // aggregated output (layers 1,2)
__device__ float g_als[(size_t)N_NODES * 6];
__device__ float g_ald[(size_t)N_NODES * 6];
__device__ float g_w3cat[384 * 40];             // folded W3 (head-mean included)
__device__ float g_bs[64 * 6];                  // W3 @ a3s per head
__device__ float g_bd[64 * 6];                  // W3 @ a3d per head
__device__ int   g_counts[N_NODES];
__device__ int   g_cursor[N_NODES];
__device__ int   g_offsets[N_NODES + 1];
__device__ int   g_csr[E_TOT];
__device__ int   g_bsum[SCAN_NB];
__device__ int   g_bpre[SCAN_NB];
__device__ int   g_idx64;

// ---------------- dtype detect ----------------
__global__ void detect_idx_kernel(const int* p) {
    int lane = threadIdx.x;
    int bad = 0;
    #pragma unroll
    for (int r = 0; r < 8; r++) {
        int i = lane + r * 32;
        if (p[2 * i + 1] != 0) bad = 1;
    }
    bad = __any_sync(0xffffffffu, bad);
    if (lane == 0) g_idx64 = bad ? 0 : 1;
}

__device__ __forceinline__ void load_edge(const void* ei, int i, int& src, int& dst) {
    if (i < N_EDGES) {
        if (g_idx64) {
            const long long* q = (const long long*)ei;
            src = (int)q[i];
            dst = (int)q[(size_t)N_EDGES + i];
        } else {
            const int* q = (const int*)ei;
            src = q[i];
            dst = q[N_EDGES + i];
        }
    } else {
        src = dst = i - N_EDGES;  // self loop
    }
}

__global__ void count_kernel(const void* ei) {
    int i = blockIdx.x * blockDim.x + threadIdx.x;
    if (i >= E_TOT) return;
    int src, dst;
    load_edge(ei, i, src, dst);
    atomicAdd(&g_counts[dst], 1);
}

// ---------------- 3-stage parallel exclusive scan ----------------
__global__ void bsum_kernel() {
    int b = blockIdx.x, t = threadIdx.x;
    int idx = b * SCAN_B + t;
    int v = (idx < N_NODES) ? g_counts[idx] : 0;
    #pragma unroll
    for (int o = 16; o > 0; o >>= 1) v += __shfl_xor_sync(0xffffffffu, v, o);
    __shared__ int ws[SCAN_B / 32];
    if ((t & 31) == 0) ws[t >> 5] = v;
    __syncthreads();
    if (t < SCAN_B / 32) {
        int s = ws[t];
        #pragma unroll
        for (int o = SCAN_B / 64; o > 0; o >>= 1) s += __shfl_xor_sync(0xffu, s, o);
        if (t == 0) g_bsum[b] = s;
    }
}

__global__ void bscan_kernel() {
    __shared__ int sm[SCAN_B];
    int t = threadIdx.x;
    int v = (t < SCAN_NB) ? g_bsum[t] : 0;
    sm[t] = v;
    __syncthreads();
    #pragma unroll
    for (int off = 1; off < SCAN_B; off <<= 1) {
        int u = (t >= off) ? sm[t - off] : 0;
        __syncthreads();
        sm[t] += u;
        __syncthreads();
    }
    if (t < SCAN_NB) g_bpre[t] = sm[t] - v;
}

__global__ void offsets_kernel() {
    __shared__ int sm[SCAN_B];
    int b = blockIdx.x, t = threadIdx.x;
    int idx = b * SCAN_B + t;
    int v = (idx < N_NODES) ? g_counts[idx] : 0;
    sm[t] = v;
    __syncthreads();
    #pragma unroll
    for (int off = 1; off < SCAN_B; off <<= 1) {
        int u = (t >= off) ? sm[t - off] : 0;
        __syncthreads();
        sm[t] += u;
        __syncthreads();
    }
    int excl = sm[t] - v + g_bpre[b];
    if (idx < N_NODES) {
        g_offsets[idx] = excl;
        g_cursor[idx] = excl;
    }
    if (idx == 0) g_offsets[N_NODES] = E_TOT;
}

__global__ void fill_kernel(const void* ei) {
    int i = blockIdx.x * blockDim.x + threadIdx.x;
    if (i >= E_TOT) return;
    int src, dst;
    load_edge(ei, i, src, dst);
    int pos = atomicAdd(&g_cursor[dst], 1);
    g_csr[pos] = src;
}

// ---------------- layer-3 prep: fold attention vecs and head-mean into W3 ----------------
__global__ void prep3_kernel(const float* __restrict__ W3, const float* __restrict__ a3s,
                             const float* __restrict__ a3d) {
    int t = blockIdx.x * blockDim.x + threadIdx.x;
    if (t >= 384) return;
    int k = t / 6, h = t % 6;
    float ss = 0.f, sd = 0.f;
    #pragma unroll
    for (int c = 0; c < 40; c++) {
        float w = W3[k * 240 + h * 40 + c];
        ss += w * a3s[h * 40 + c];
        sd += w * a3d[h * 40 + c];
    }
    g_bs[k * 6 + h] = ss;
    g_bd[k * 6 + h] = sd;
}

__global__ void prep_wcat_kernel(const float* __restrict__ W3) {
    int i = blockIdx.x * blockDim.x + threadIdx.x;
    if (i >= 384 * 40) return;
    int hk = i / 40, c = i % 40;
    int h = hk >> 6, k = hk & 63;
    g_w3cat[i] = W3[k * 240 + h * 40 + c] * (1.f / 6.f);
}

// als/ald[n, 0..5] = x[n,:] @ Bs / Bd
__global__ void logit3_kernel(const float* __restrict__ X) {
    __shared__ float xs[64 * 65];
    __shared__ float Bsm[64 * 12];
    int tid = threadIdx.x;
    int n0 = blockIdx.x * 64;
    for (int i = tid; i < 768; i += 256) {
        int k = i / 12, j = i % 12;
        Bsm[k * 12 + j] = (j < 6) ? g_bs[k * 6 + j] : g_bd[k * 6 + (j - 6)];
    }
    for (int i = tid; i < 64 * 64; i += 256) {
        int m = i >> 6, k = i & 63;
        int gm = n0 + m;
        xs[m * 65 + k] = (gm < N_NODES) ? X[(size_t)gm * 64 + k] : 0.f;
    }
    __syncthreads();
    for (int p = tid; p < 768; p += 256) {
        int m = p / 12, j = p % 12;
        float s = 0.f;
        #pragma unroll
        for (int k = 0; k < 64; k++) s = fmaf(xs[m * 65 + k], Bsm[k * 12 + j], s);
        int gm = n0 + m;
        if (gm < N_NODES) {
            if (j < 6) g_als[gm * 6 + j] = s;
            else       g_ald[gm * 6 + (j - 6)] = s;
        }
    }
}

// ---------------- fused GEMM + attention-logit kernel (layers 1,2) ----------------
// 256 threads: TM=4 rows/thread (MTH=32), TF=8 cols/thread (FTH=8 for F=64).
template <int K, int F, int BM, int TM, int TF, int H>
__global__ void gemm_al_kernel(const float* __restrict__ X, const float* __restrict__ W,
                               const float* __restrict__ Avs, const float* __restrict__ Avd,
                               float* __restrict__ Ho, float* __restrict__ als,
                               float* __restrict__ ald, int Nn) {
    constexpr int MTH = BM / TM;          // 32
    constexpr int FTH = F / TF;           // 8
    constexpr int NTH = MTH * FTH;        // 256
    constexpr int C = F / H;
    constexpr int XLD = K + 1;
    extern __shared__ float sh[];
    float* ws = sh;
    float* xs = ws + K * F;
    float* asum = xs + BM * XLD;

    int tid = threadIdx.x;
    for (int i = tid; i < K * F; i += NTH) ws[i] = W[i];

    int mx = tid % MTH;
    int fx = tid / MTH;
    int f0 = fx * TF;
    int headT = f0 / C;
    float ras[TF], rad[TF];
    #pragma unroll
    for (int j = 0; j < TF; j++) { ras[j] = Avs[f0 + j]; rad[j] = Avd[f0 + j]; }

    int tile = blockIdx.x * BM;
    {
        __syncthreads();
        for (int i = tid; i < BM * K; i += NTH) {
            int m = i / K, k = i - m * K;
            int gm = tile + m;
            xs[m * XLD + k] = (gm < Nn) ? X[(size_t)gm * K + k] : 0.f;
        }
        for (int i = tid; i < BM * 2 * H; i += NTH) asum[i] = 0.f;
        __syncthreads();

        float acc[TM][TF];
        #pragma unroll
        for (int i = 0; i < TM; i++)
            #pragma unroll
            for (int j = 0; j < TF; j++) acc[i][j] = 0.f;

        #pragma unroll 4
        for (int k = 0; k < K; k++) {
            float xv[TM];
            #pragma unroll
            for (int i = 0; i < TM; i++) xv[i] = xs[(mx + i * MTH) * XLD + k];
            float wv[TF];
            #pragma unroll
            for (int j4 = 0; j4 < TF / 4; j4++) {
                float4 w4 = *reinterpret_cast<const float4*>(&ws[k * F + f0 + j4 * 4]);
                wv[j4 * 4 + 0] = w4.x; wv[j4 * 4 + 1] = w4.y;
                wv[j4 * 4 + 2] = w4.z; wv[j4 * 4 + 3] = w4.w;
            }
            #pragma unroll
            for (int i = 0; i < TM; i++)
                #pragma unroll
                for (int j = 0; j < TF; j++) acc[i][j] = fmaf(xv[i], wv[j], acc[i][j]);
        }

        #pragma unroll
        for (int i = 0; i < TM; i++) {
            int m = mx + i * MTH;
            int gm = tile + m;
            if (gm < Nn) {
                float ss = 0.f, sd = 0.f;
                #pragma unroll
                for (int j4 = 0; j4 < TF / 4; j4++) {
                    float4 o4;
                    o4.x = acc[i][j4 * 4 + 0]; o4.y = acc[i][j4 * 4 + 1];
                    o4.z = acc[i][j4 * 4 + 2]; o4.w = acc[i][j4 * 4 + 3];
                    *reinterpret_cast<float4*>(&Ho[(size_t)gm * F + f0 + j4 * 4]) = o4;
                }
                #pragma unroll
                for (int j = 0; j < TF; j++) {
                    ss += acc[i][j] * ras[j];
                    sd += acc[i][j] * rad[j];
                }
                atomicAdd(&asum[m * 2 * H + headT], ss);
                atomicAdd(&asum[m * 2 * H + H + headT], sd);
            }
        }
        __syncthreads();
        for (int i = tid; i < BM * H; i += NTH) {
            int m = i / H, hh = i - m * H;
            int gm = tile + m;
            if (gm < Nn) {
                als[gm * H + hh] = asum[m * 2 * H + hh];
                ald[gm * H + hh] = asum[m * 2 * H + H + hh];
            }
        }
    }
}

// ---------------- layers 1/2 aggregation: ONE edge sweep per warp-per-node ----------------
// Each lane owns channels ch=lane*2 (+1) of one head hr=ch/16; recomputes its
// head's exp weight per edge (broadcast 1-sector als load) while accumulating
// both the un-normalized feature sum and the softmax denominator.
__global__ void agg12_kernel(const float* __restrict__ h, const float* __restrict__ als,
                             const float* __restrict__ ald, const float* __restrict__ bias,
                             float* __restrict__ out) {
    int gw = (blockIdx.x * blockDim.x + threadIdx.x) >> 5;
    if (gw >= N_NODES) return;
    int lane = threadIdx.x & 31;
    int beg = g_offsets[gw], end = g_offsets[gw + 1];

    int ch = lane * 2;
    int hr = ch >> 4;  // C=16
    float aldv = __ldg(&ald[gw * 4 + hr]);

    float2 acc = make_float2(0.f, 0.f);
    float ssum = 0.f;
    #pragma unroll 2
    for (int i = beg; i < end; i++) {
        int s = g_csr[i];  // warp-uniform
        float e = __ldg(&als[s * 4 + hr]) + aldv;
        e = e > 0.f ? e : 0.2f * e;
        float w = __expf(e);
        ssum += w;
        float2 hv = *reinterpret_cast<const float2*>(&h[(size_t)s * 64 + ch]);
        acc.x = fmaf(w, hv.x, acc.x);
        acc.y = fmaf(w, hv.y, acc.y);
    }
    float inv = 1.f / ssum;
    float vx = acc.x * inv + bias[ch];
    float vy = acc.y * inv + bias[ch + 1];
    vx = vx > 0.f ? vx : (__expf(vx) - 1.f);
    vy = vy > 0.f ? vy : (__expf(vy) - 1.f);
    *reinterpret_cast<float2*>(&out[(size_t)gw * 64 + ch]) = make_float2(vx, vy);
}

// ---------------- layer-3 aggregation in input space, ONE edge sweep ----------------
// aggx[d, h*64+k] = (1/sum_h) * sum_e exp(leaky(e))_h * x[src_e, k]
__global__ void agg3x_kernel(const float* __restrict__ x, const float* __restrict__ als,
                             const float* __restrict__ ald, float* __restrict__ aggx) {
    int gw = (blockIdx.x * blockDim.x + threadIdx.x) >> 5;
    if (gw >= N_NODES) return;
    int lane = threadIdx.x & 31;
    int beg = g_offsets[gw], end = g_offsets[gw + 1];

    float aldh[6];
    #pragma unroll
    for (int q = 0; q < 3; q++) {
        float2 t = *reinterpret_cast<const float2*>(&ald[gw * 6 + 2 * q]);
        aldh[2 * q] = t.x; aldh[2 * q + 1] = t.y;
    }

    int ch = lane * 2;
    float2 acc[6];
    float sv[6];
    #pragma unroll
    for (int hh = 0; hh < 6; hh++) { acc[hh] = make_float2(0.f, 0.f); sv[hh] = 0.f; }

    #pragma unroll 2
    for (int i = beg; i < end; i++) {
        int s = g_csr[i];  // warp-uniform -> als loads are broadcast
        float av[6];
        #pragma unroll
        for (int q = 0; q < 3; q++) {
            float2 t = *reinterpret_cast<const float2*>(&als[s * 6 + 2 * q]);
            av[2 * q] = t.x; av[2 * q + 1] = t.y;
        }
        float w[6];
        #pragma unroll
        for (int hh = 0; hh < 6; hh++) {
            float e = av[hh] + aldh[hh];
            e = e > 0.f ? e : 0.2f * e;
            float xv = __expf(e);
            w[hh] = xv;
            sv[hh] += xv;
        }
        float2 hv = *reinterpret_cast<const float2*>(&x[(size_t)s * 64 + ch]);
        #pragma unroll
        for (int hh = 0; hh < 6; hh++) {
            acc[hh].x = fmaf(w[hh], hv.x, acc[hh].x);
            acc[hh].y = fmaf(w[hh], hv.y, acc[hh].y);
        }
    }

    size_t base = (size_t)gw * 384;
    #pragma unroll
    for (int hh = 0; hh < 6; hh++) {
        float inv = 1.f / sv[hh];
        *reinterpret_cast<float2*>(&aggx[base + hh * 64 + ch]) =
            make_float2(acc[hh].x * inv, acc[hh].y * inv);
    }
}

// ---------------- final GEMM: [N,384] @ Wcat[384,40] + bias + elu + log_softmax ----------------
// 256 threads: TM=4 (MTH=32), TF=5 (FTH=8).
__global__ void gemm_final_kernel(const float* __restrict__ X, const float* __restrict__ b3,
                                  float* __restrict__ out, int Nn) {
    constexpr int BM = 128, BK = 64, Ktot = 384, F = 40;
    constexpr int TM = 4, TF = 5, MTH = 32, NTH = 256;
    extern __shared__ float sh[];
    float* ws = sh;              // 384*40
    float* xs = ws + Ktot * F;   // BM*(BK+1)

    int tid = threadIdx.x;
    for (int i = tid; i < Ktot * F; i += NTH) ws[i] = g_w3cat[i];

    int mx = tid % MTH;
    int fx = tid / MTH;
    int f0 = fx * TF;
    int tile = blockIdx.x * BM;

    float acc[TM][TF];
    #pragma unroll
    for (int i = 0; i < TM; i++)
        #pragma unroll
        for (int j = 0; j < TF; j++) acc[i][j] = 0.f;

    for (int kt = 0; kt < Ktot; kt += BK) {
        __syncthreads();
        for (int i = tid; i < BM * BK; i += NTH) {
            int m = i / BK, k = i - m * BK;
            int gm = tile + m;
            xs[m * (BK + 1) + k] = (gm < Nn) ? X[(size_t)gm * Ktot + kt + k] : 0.f;
        }
        __syncthreads();
        #pragma unroll 4
        for (int k = 0; k < BK; k++) {
            float xv[TM];
            #pragma unroll
            for (int i = 0; i < TM; i++) xv[i] = xs[(mx + i * MTH) * (BK + 1) + k];
            float wv[TF];
            #pragma unroll
            for (int j = 0; j < TF; j++) wv[j] = ws[(kt + k) * F + f0 + j];
            #pragma unroll
            for (int i = 0; i < TM; i++)
                #pragma unroll
                for (int j = 0; j < TF; j++) acc[i][j] = fmaf(xv[i], wv[j], acc[i][j]);
        }
    }

    // epilogue: bias + elu + per-row log_softmax
    __syncthreads();
    float* sbuf = xs;              // BM*40
    float* lrow = xs + BM * F;     // BM
    #pragma unroll
    for (int i = 0; i < TM; i++) {
        int m = mx + i * MTH;
        #pragma unroll
        for (int j = 0; j < TF; j++)
            sbuf[m * F + f0 + j] = acc[i][j] + b3[f0 + j];
    }
    __syncthreads();
    if (tid < BM) {
        int m = tid;
        float mxv = -1e30f;
        #pragma unroll 4
        for (int c = 0; c < F; c++) {
            float v = sbuf[m * F + c];
            v = v > 0.f ? v : (__expf(v) - 1.f);
            sbuf[m * F + c] = v;
            mxv = fmaxf(mxv, v);
        }
        float se = 0.f;
        #pragma unroll 4
        for (int c = 0; c < F; c++) se += __expf(sbuf[m * F + c] - mxv);
        lrow[m] = __logf(se) + mxv;
    }
    __syncthreads();
    for (int i = tid; i < BM * F; i += NTH) {
        int m = i / F;
        int gm = tile + m;
        if (gm < Nn) out[(size_t)gm * F + (i - m * F)] = sbuf[i] - lrow[m];
    }
}

// ---------------- host launcher ----------------
extern "C" void kernel_launch(void* const* d_in, const int* in_sizes, int n_in,
                              void* d_out, int out_size) {
    const float* x   = (const float*)d_in[0];
    const void*  ei  = d_in[1];
    const float* W1  = (const float*)d_in[2];
    const float* a1s = (const float*)d_in[3];
    const float* a1d = (const float*)d_in[4];
    const float* b1  = (const float*)d_in[5];
    const float* W2  = (const float*)d_in[6];
    const float* a2s = (const float*)d_in[7];
    const float* a2d = (const float*)d_in[8];
    const float* b2  = (const float*)d_in[9];
    const float* W3  = (const float*)d_in[10];
    const float* a3s = (const float*)d_in[11];
    const float* a3d = (const float*)d_in[12];
    const float* b3  = (const float*)d_in[13];
    float* out = (float*)d_out;

    float *p_h, *p_agg, *p_als, *p_ald;
    int *p_counts;
    cudaGetSymbolAddress((void**)&p_h, g_h);
    cudaGetSymbolAddress((void**)&p_agg, g_agg);
    cudaGetSymbolAddress((void**)&p_als, g_als);
    cudaGetSymbolAddress((void**)&p_ald, g_ald);
    cudaGetSymbolAddress((void**)&p_counts, g_counts);

    // ---- CSR build + layer-3 weight folding ----
    detect_idx_kernel<<<1, 32>>>((const int*)ei);
    cudaMemsetAsync(p_counts, 0, N_NODES * sizeof(int));
    prep3_kernel<<<2, 256>>>(W3, a3s, a3d);
    prep_wcat_kernel<<<(384 * 40 + 255) / 256, 256>>>(W3);
    count_kernel<<<(E_TOT + 255) / 256, 256>>>(ei);
    bsum_kernel<<<SCAN_NB, SCAN_B>>>();
    bscan_kernel<<<1, SCAN_B>>>();
    offsets_kernel<<<SCAN_NB, SCAN_B>>>();
    fill_kernel<<<(E_TOT + 255) / 256, 256>>>(ei);

    const int AGG_GRID = (N_NODES * 32 + 255) / 256;

    // ---- layer 1: 128 -> 4x16 concat ----
    {
        constexpr int K = 128, F = 64, BM = 128, TM = 4, TF = 8, H = 4;
        size_t smem = (size_t)(K * F + BM * (K + 1) + BM * 2 * H) * sizeof(float);
        cudaFuncSetAttribute(gemm_al_kernel<K, F, BM, TM, TF, H>,
                             cudaFuncAttributeMaxDynamicSharedMemorySize, (int)smem);
        int grid = (N_NODES + BM - 1) / BM;
        gemm_al_kernel<K, F, BM, TM, TF, H><<<grid, (BM / TM) * (F / TF), smem>>>(
            x, W1, a1s, a1d, p_h, p_als, p_ald, N_NODES);
        agg12_kernel<<<AGG_GRID, 256>>>(p_h, p_als, p_ald, b1, p_agg);
    }

    // ---- layer 2: 64 -> 4x16 concat ----
    {
        constexpr int K = 64, F = 64, BM = 128, TM = 4, TF = 8, H = 4;
        size_t smem = (size_t)(K * F + BM * (K + 1) + BM * 2 * H) * sizeof(float);
        cudaFuncSetAttribute(gemm_al_kernel<K, F, BM, TM, TF, H>,
                             cudaFuncAttributeMaxDynamicSharedMemorySize, (int)smem);
        int grid = (N_NODES + BM - 1) / BM;
        gemm_al_kernel<K, F, BM, TM, TF, H><<<grid, (BM / TM) * (F / TF), smem>>>(
            p_agg, W2, a2s, a2d, p_h, p_als, p_ald, N_NODES);
        agg12_kernel<<<AGG_GRID, 256>>>(p_h, p_als, p_ald, b2, p_agg);
    }

    // ---- layer 3: logits from x, aggregate x per head, folded GEMM + softmax ----
    logit3_kernel<<<(N_NODES + 63) / 64, 256>>>(p_agg);
    agg3x_kernel<<<AGG_GRID, 256>>>(p_agg, p_als, p_ald, p_h);
    {
        size_t smem = (size_t)(384 * 40 + 128 * 65) * sizeof(float);
        cudaFuncSetAttribute(gemm_final_kernel,
                             cudaFuncAttributeMaxDynamicSharedMemorySize, (int)smem);
        gemm_final_kernel<<<(N_NODES + 127) / 128, 256, smem>>>(p_h, b3, out, N_NODES);
    }
}

// round 7
// speedup vs baseline: 1.1639x; 1.0931x over previous
#include <cuda_runtime.h>
#include <cuda_fp16.h>
#include <cstdint>

// ---------------- problem constants ----------------
#define N_NODES 50000
#define N_EDGES 1600000
#define E_TOT   (N_EDGES + N_NODES)   // + self loops
#define F_IN    128

#define SCAN_B   256
#define SCAN_NB  ((N_NODES + SCAN_B - 1) / SCAN_B)   // 196

// ---------------- device scratch ----------------
__device__ float  g_aggx[(size_t)N_NODES * 384];  // layer-3 per-head aggregated x
__device__ float  g_agg[(size_t)N_NODES * 64];    // layer-1 agg output (fp32, GEMM input)
__device__ __half g_hh[(size_t)N_NODES * 64];     // GEMM feature output (gathered), fp16
__device__ __half g_x2h[(size_t)N_NODES * 64];    // layer-2 agg output (gathered), fp16
__device__ float  g_als[(size_t)N_NODES * 6];
__device__ float  g_ald[(size_t)N_NODES * 6];
__device__ float  g_w3cat[384 * 40];              // folded W3 (head-mean included)
__device__ float  g_bs[64 * 6];
__device__ float  g_bd[64 * 6];
__device__ int    g_counts[N_NODES];
__device__ int    g_cursor[N_NODES];
__device__ int    g_offsets[N_NODES + 1];
__device__ int    g_csr[E_TOT];
__device__ int    g_bsum[SCAN_NB];
__device__ int    g_bpre[SCAN_NB];
__device__ int    g_idx64;

// ---------------- dtype detect ----------------
__global__ void detect_idx_kernel(const int* p) {
    int lane = threadIdx.x;
    int bad = 0;
    #pragma unroll
    for (int r = 0; r < 8; r++) {
        int i = lane + r * 32;
        if (p[2 * i + 1] != 0) bad = 1;
    }
    bad = __any_sync(0xffffffffu, bad);
    if (lane == 0) g_idx64 = bad ? 0 : 1;
}

__device__ __forceinline__ void load_edge(const void* ei, int i, int& src, int& dst) {
    if (i < N_EDGES) {
        if (g_idx64) {
            const long long* q = (const long long*)ei;
            src = (int)q[i];
            dst = (int)q[(size_t)N_EDGES + i];
        } else {
            const int* q = (const int*)ei;
            src = q[i];
            dst = q[N_EDGES + i];
        }
    } else {
        src = dst = i - N_EDGES;  // self loop
    }
}

__global__ void count_kernel(const void* ei) {
    int i = blockIdx.x * blockDim.x + threadIdx.x;
    if (i >= E_TOT) return;
    int src, dst;
    load_edge(ei, i, src, dst);
    atomicAdd(&g_counts[dst], 1);
}

// ---------------- 3-stage parallel exclusive scan ----------------
__global__ void bsum_kernel() {
    int b = blockIdx.x, t = threadIdx.x;
    int idx = b * SCAN_B + t;
    int v = (idx < N_NODES) ? g_counts[idx] : 0;
    #pragma unroll
    for (int o = 16; o > 0; o >>= 1) v += __shfl_xor_sync(0xffffffffu, v, o);
    __shared__ int ws[SCAN_B / 32];
    if ((t & 31) == 0) ws[t >> 5] = v;
    __syncthreads();
    if (t < SCAN_B / 32) {
        int s = ws[t];
        #pragma unroll
        for (int o = SCAN_B / 64; o > 0; o >>= 1) s += __shfl_xor_sync(0xffu, s, o);
        if (t == 0) g_bsum[b] = s;
    }
}

__global__ void bscan_kernel() {
    __shared__ int sm[SCAN_B];
    int t = threadIdx.x;
    int v = (t < SCAN_NB) ? g_bsum[t] : 0;
    sm[t] = v;
    __syncthreads();
    #pragma unroll
    for (int off = 1; off < SCAN_B; off <<= 1) {
        int u = (t >= off) ? sm[t - off] : 0;
        __syncthreads();
        sm[t] += u;
        __syncthreads();
    }
    if (t < SCAN_NB) g_bpre[t] = sm[t] - v;
}

__global__ void offsets_kernel() {
    __shared__ int sm[SCAN_B];
    int b = blockIdx.x, t = threadIdx.x;
    int idx = b * SCAN_B + t;
    int v = (idx < N_NODES) ? g_counts[idx] : 0;
    sm[t] = v;
    __syncthreads();
    #pragma unroll
    for (int off = 1; off < SCAN_B; off <<= 1) {
        int u = (t >= off) ? sm[t - off] : 0;
        __syncthreads();
        sm[t] += u;
        __syncthreads();
    }
    int excl = sm[t] - v + g_bpre[b];
    if (idx < N_NODES) {
        g_offsets[idx] = excl;
        g_cursor[idx] = excl;
    }
    if (idx == 0) g_offsets[N_NODES] = E_TOT;
}

__global__ void fill_kernel(const void* ei) {
    int i = blockIdx.x * blockDim.x + threadIdx.x;
    if (i >= E_TOT) return;
    int src, dst;
    load_edge(ei, i, src, dst);
    int pos = atomicAdd(&g_cursor[dst], 1);
    g_csr[pos] = src;
}

// ---------------- layer-3 prep: fold attention vecs and head-mean into W3 ----------------
__global__ void prep3_kernel(const float* __restrict__ W3, const float* __restrict__ a3s,
                             const float* __restrict__ a3d) {
    int t = blockIdx.x * blockDim.x + threadIdx.x;
    if (t >= 384) return;
    int k = t / 6, h = t % 6;
    float ss = 0.f, sd = 0.f;
    #pragma unroll
    for (int c = 0; c < 40; c++) {
        float w = W3[k * 240 + h * 40 + c];
        ss += w * a3s[h * 40 + c];
        sd += w * a3d[h * 40 + c];
    }
    g_bs[k * 6 + h] = ss;
    g_bd[k * 6 + h] = sd;
}

__global__ void prep_wcat_kernel(const float* __restrict__ W3) {
    int i = blockIdx.x * blockDim.x + threadIdx.x;
    if (i >= 384 * 40) return;
    int hk = i / 40, c = i % 40;
    int h = hk >> 6, k = hk & 63;
    g_w3cat[i] = W3[k * 240 + h * 40 + c] * (1.f / 6.f);
}

// als/ald[n, 0..5] = x[n,:] @ Bs / Bd   (x is layer-2 output, fp16)
__global__ void logit3_kernel(const __half* __restrict__ X) {
    __shared__ float xs[64 * 65];
    __shared__ float Bsm[64 * 12];
    int tid = threadIdx.x;
    int n0 = blockIdx.x * 64;
    for (int i = tid; i < 768; i += 256) {
        int k = i / 12, j = i % 12;
        Bsm[k * 12 + j] = (j < 6) ? g_bs[k * 6 + j] : g_bd[k * 6 + (j - 6)];
    }
    for (int i = tid; i < 64 * 32; i += 256) {
        int m = i >> 5, k2 = (i & 31) * 2;
        int gm = n0 + m;
        float2 v = make_float2(0.f, 0.f);
        if (gm < N_NODES)
            v = __half22float2(*reinterpret_cast<const __half2*>(&X[(size_t)gm * 64 + k2]));
        xs[m * 65 + k2] = v.x;
        xs[m * 65 + k2 + 1] = v.y;
    }
    __syncthreads();
    for (int p = tid; p < 768; p += 256) {
        int m = p / 12, j = p % 12;
        float s = 0.f;
        #pragma unroll
        for (int k = 0; k < 64; k++) s = fmaf(xs[m * 65 + k], Bsm[k * 12 + j], s);
        int gm = n0 + m;
        if (gm < N_NODES) {
            if (j < 6) g_als[gm * 6 + j] = s;
            else       g_ald[gm * 6 + (j - 6)] = s;
        }
    }
}

// ---------------- fused GEMM + attention-logit kernel (layers 1,2) ----------------
// 256 threads; writes h as fp16 (gather format) + per-node logits.
template <int K, int F, int BM, int TM, int TF, int H>
__global__ void gemm_al_kernel(const float* __restrict__ X, const float* __restrict__ W,
                               const float* __restrict__ Avs, const float* __restrict__ Avd,
                               __half* __restrict__ Ho, float* __restrict__ als,
                               float* __restrict__ ald, int Nn) {
    constexpr int MTH = BM / TM;
    constexpr int FTH = F / TF;
    constexpr int NTH = MTH * FTH;
    constexpr int C = F / H;
    constexpr int XLD = K + 1;
    extern __shared__ float sh[];
    float* ws = sh;
    float* xs = ws + K * F;
    float* asum = xs + BM * XLD;

    int tid = threadIdx.x;
    for (int i = tid; i < K * F; i += NTH) ws[i] = W[i];

    int mx = tid % MTH;
    int fx = tid / MTH;
    int f0 = fx * TF;
    int headT = f0 / C;
    float ras[TF], rad[TF];
    #pragma unroll
    for (int j = 0; j < TF; j++) { ras[j] = Avs[f0 + j]; rad[j] = Avd[f0 + j]; }

    int tile = blockIdx.x * BM;
    __syncthreads();
    for (int i = tid; i < BM * K; i += NTH) {
        int m = i / K, k = i - m * K;
        int gm = tile + m;
        xs[m * XLD + k] = (gm < Nn) ? X[(size_t)gm * K + k] : 0.f;
    }
    for (int i = tid; i < BM * 2 * H; i += NTH) asum[i] = 0.f;
    __syncthreads();

    float acc[TM][TF];
    #pragma unroll
    for (int i = 0; i < TM; i++)
        #pragma unroll
        for (int j = 0; j < TF; j++) acc[i][j] = 0.f;

    #pragma unroll 4
    for (int k = 0; k < K; k++) {
        float xv[TM];
        #pragma unroll
        for (int i = 0; i < TM; i++) xv[i] = xs[(mx + i * MTH) * XLD + k];
        float wv[TF];
        #pragma unroll
        for (int j4 = 0; j4 < TF / 4; j4++) {
            float4 w4 = *reinterpret_cast<const float4*>(&ws[k * F + f0 + j4 * 4]);
            wv[j4 * 4 + 0] = w4.x; wv[j4 * 4 + 1] = w4.y;
            wv[j4 * 4 + 2] = w4.z; wv[j4 * 4 + 3] = w4.w;
        }
        #pragma unroll
        for (int i = 0; i < TM; i++)
            #pragma unroll
            for (int j = 0; j < TF; j++) acc[i][j] = fmaf(xv[i], wv[j], acc[i][j]);
    }

    #pragma unroll
    for (int i = 0; i < TM; i++) {
        int m = mx + i * MTH;
        int gm = tile + m;
        if (gm < Nn) {
            // pack TF=8 halves into one 16B store
            __half2 p[TF / 2];
            #pragma unroll
            for (int q = 0; q < TF / 2; q++)
                p[q] = __floats2half2_rn(acc[i][2 * q], acc[i][2 * q + 1]);
            uint4 u;
            u.x = *reinterpret_cast<unsigned*>(&p[0]);
            u.y = *reinterpret_cast<unsigned*>(&p[1]);
            u.z = *reinterpret_cast<unsigned*>(&p[2]);
            u.w = *reinterpret_cast<unsigned*>(&p[3]);
            *reinterpret_cast<uint4*>(&Ho[(size_t)gm * F + f0]) = u;

            float ss = 0.f, sd = 0.f;
            #pragma unroll
            for (int j = 0; j < TF; j++) {
                ss += acc[i][j] * ras[j];
                sd += acc[i][j] * rad[j];
            }
            atomicAdd(&asum[m * 2 * H + headT], ss);
            atomicAdd(&asum[m * 2 * H + H + headT], sd);
        }
    }
    __syncthreads();
    for (int i = tid; i < BM * H; i += NTH) {
        int m = i / H, hh = i - m * H;
        int gm = tile + m;
        if (gm < Nn) {
            als[gm * H + hh] = asum[m * 2 * H + hh];
            ald[gm * H + hh] = asum[m * 2 * H + H + hh];
        }
    }
}

// ---------------- layers 1/2 aggregation: one warp per node, fp16 gather ----------------
template <bool OUT_HALF>
__global__ void agg12_kernel(const __half* __restrict__ h, const float* __restrict__ als,
                             const float* __restrict__ ald, const float* __restrict__ bias,
                             void* __restrict__ outv) {
    int gw = (blockIdx.x * blockDim.x + threadIdx.x) >> 5;
    if (gw >= N_NODES) return;
    int lane = threadIdx.x & 31;
    int beg = g_offsets[gw], end = g_offsets[gw + 1];

    int ch = lane * 2;
    int hr = ch >> 4;  // C=16
    float aldv = __ldg(&ald[gw * 4 + hr]);

    float2 acc = make_float2(0.f, 0.f);
    float ssum = 0.f;
    #pragma unroll 2
    for (int i = beg; i < end; i++) {
        int s = g_csr[i];  // warp-uniform
        float e = __ldg(&als[s * 4 + hr]) + aldv;
        e = e > 0.f ? e : 0.2f * e;
        float w = __expf(e);
        ssum += w;
        float2 hv = __half22float2(*reinterpret_cast<const __half2*>(&h[(size_t)s * 64 + ch]));
        acc.x = fmaf(w, hv.x, acc.x);
        acc.y = fmaf(w, hv.y, acc.y);
    }
    float inv = 1.f / ssum;
    float vx = acc.x * inv + bias[ch];
    float vy = acc.y * inv + bias[ch + 1];
    vx = vx > 0.f ? vx : (__expf(vx) - 1.f);
    vy = vy > 0.f ? vy : (__expf(vy) - 1.f);
    if (OUT_HALF) {
        *reinterpret_cast<__half2*>(&((__half*)outv)[(size_t)gw * 64 + ch]) =
            __floats2half2_rn(vx, vy);
    } else {
        *reinterpret_cast<float2*>(&((float*)outv)[(size_t)gw * 64 + ch]) =
            make_float2(vx, vy);
    }
}

// ---------------- layer-3 aggregation in input space: shfl-staged weights ----------------
// Stage 1 (per 32-edge chunk): lane e computes all 6 exp-weights for its edge.
// Stage 2: warp iterates the chunk; src + 6 weights broadcast via shfl.
__global__ void agg3x_kernel(const __half* __restrict__ x, const float* __restrict__ als,
                             const float* __restrict__ ald, float* __restrict__ aggx) {
    int gw = (blockIdx.x * blockDim.x + threadIdx.x) >> 5;
    if (gw >= N_NODES) return;
    int lane = threadIdx.x & 31;
    int beg = g_offsets[gw], end = g_offsets[gw + 1];

    float aldh[6];
    #pragma unroll
    for (int q = 0; q < 3; q++) {
        float2 t = *reinterpret_cast<const float2*>(&ald[gw * 6 + 2 * q]);
        aldh[2 * q] = t.x; aldh[2 * q + 1] = t.y;
    }

    int ch = lane * 2;
    float2 acc[6];
    float sv[6];
    #pragma unroll
    for (int hh = 0; hh < 6; hh++) { acc[hh] = make_float2(0.f, 0.f); sv[hh] = 0.f; }

    for (int base = beg; base < end; base += 32) {
        int i = base + lane;
        int sreg = 0;
        float w[6];
        #pragma unroll
        for (int hh = 0; hh < 6; hh++) w[hh] = 0.f;
        if (i < end) {
            sreg = g_csr[i];
            #pragma unroll
            for (int q = 0; q < 3; q++) {
                float2 t = __ldg(reinterpret_cast<const float2*>(&als[sreg * 6 + 2 * q]));
                float e0 = t.x + aldh[2 * q];
                float e1 = t.y + aldh[2 * q + 1];
                e0 = e0 > 0.f ? e0 : 0.2f * e0;
                e1 = e1 > 0.f ? e1 : 0.2f * e1;
                w[2 * q] = __expf(e0);
                w[2 * q + 1] = __expf(e1);
            }
            #pragma unroll
            for (int hh = 0; hh < 6; hh++) sv[hh] += w[hh];
        }
        int cnt = min(32, end - base);
        for (int j = 0; j < cnt; j++) {
            int s = __shfl_sync(0xffffffffu, sreg, j);
            float w0 = __shfl_sync(0xffffffffu, w[0], j);
            float w1 = __shfl_sync(0xffffffffu, w[1], j);
            float w2 = __shfl_sync(0xffffffffu, w[2], j);
            float w3 = __shfl_sync(0xffffffffu, w[3], j);
            float w4 = __shfl_sync(0xffffffffu, w[4], j);
            float w5 = __shfl_sync(0xffffffffu, w[5], j);
            float2 hv = __half22float2(
                *reinterpret_cast<const __half2*>(&x[(size_t)s * 64 + ch]));
            acc[0].x = fmaf(w0, hv.x, acc[0].x); acc[0].y = fmaf(w0, hv.y, acc[0].y);
            acc[1].x = fmaf(w1, hv.x, acc[1].x); acc[1].y = fmaf(w1, hv.y, acc[1].y);
            acc[2].x = fmaf(w2, hv.x, acc[2].x); acc[2].y = fmaf(w2, hv.y, acc[2].y);
            acc[3].x = fmaf(w3, hv.x, acc[3].x); acc[3].y = fmaf(w3, hv.y, acc[3].y);
            acc[4].x = fmaf(w4, hv.x, acc[4].x); acc[4].y = fmaf(w4, hv.y, acc[4].y);
            acc[5].x = fmaf(w5, hv.x, acc[5].x); acc[5].y = fmaf(w5, hv.y, acc[5].y);
        }
    }

    // reduce denominators across lanes
    #pragma unroll
    for (int hh = 0; hh < 6; hh++)
        #pragma unroll
        for (int o = 16; o > 0; o >>= 1)
            sv[hh] += __shfl_xor_sync(0xffffffffu, sv[hh], o);

    size_t b2 = (size_t)gw * 384;
    #pragma unroll
    for (int hh = 0; hh < 6; hh++) {
        float inv = 1.f / sv[hh];
        *reinterpret_cast<float2*>(&aggx[b2 + hh * 64 + ch]) =
            make_float2(acc[hh].x * inv, acc[hh].y * inv);
    }
}

// ---------------- final GEMM: [N,384] @ Wcat[384,40] + bias + elu + log_softmax ----------------
__global__ void gemm_final_kernel(const float* __restrict__ X, const float* __restrict__ b3,
                                  float* __restrict__ out, int Nn) {
    constexpr int BM = 128, BK = 64, Ktot = 384, F = 40;
    constexpr int TM = 4, TF = 5, MTH = 32, NTH = 256;
    extern __shared__ float sh[];
    float* ws = sh;              // 384*40
    float* xs = ws + Ktot * F;   // BM*(BK+1)

    int tid = threadIdx.x;
    for (int i = tid; i < Ktot * F; i += NTH) ws[i] = g_w3cat[i];

    int mx = tid % MTH;
    int fx = tid / MTH;
    int f0 = fx * TF;
    int tile = blockIdx.x * BM;

    float acc[TM][TF];
    #pragma unroll
    for (int i = 0; i < TM; i++)
        #pragma unroll
        for (int j = 0; j < TF; j++) acc[i][j] = 0.f;

    for (int kt = 0; kt < Ktot; kt += BK) {
        __syncthreads();
        for (int i = tid; i < BM * BK; i += NTH) {
            int m = i / BK, k = i - m * BK;
            int gm = tile + m;
            xs[m * (BK + 1) + k] = (gm < Nn) ? X[(size_t)gm * Ktot + kt + k] : 0.f;
        }
        __syncthreads();
        #pragma unroll 4
        for (int k = 0; k < BK; k++) {
            float xv[TM];
            #pragma unroll
            for (int i = 0; i < TM; i++) xv[i] = xs[(mx + i * MTH) * (BK + 1) + k];
            float wv[TF];
            #pragma unroll
            for (int j = 0; j < TF; j++) wv[j] = ws[(kt + k) * F + f0 + j];
            #pragma unroll
            for (int i = 0; i < TM; i++)
                #pragma unroll
                for (int j = 0; j < TF; j++) acc[i][j] = fmaf(xv[i], wv[j], acc[i][j]);
        }
    }

    __syncthreads();
    float* sbuf = xs;              // BM*40
    float* lrow = xs + BM * F;     // BM
    #pragma unroll
    for (int i = 0; i < TM; i++) {
        int m = mx + i * MTH;
        #pragma unroll
        for (int j = 0; j < TF; j++)
            sbuf[m * F + f0 + j] = acc[i][j] + b3[f0 + j];
    }
    __syncthreads();
    if (tid < BM) {
        int m = tid;
        float mxv = -1e30f;
        #pragma unroll 4
        for (int c = 0; c < F; c++) {
            float v = sbuf[m * F + c];
            v = v > 0.f ? v : (__expf(v) - 1.f);
            sbuf[m * F + c] = v;
            mxv = fmaxf(mxv, v);
        }
        float se = 0.f;
        #pragma unroll 4
        for (int c = 0; c < F; c++) se += __expf(sbuf[m * F + c] - mxv);
        lrow[m] = __logf(se) + mxv;
    }
    __syncthreads();
    for (int i = tid; i < BM * F; i += NTH) {
        int m = i / F;
        int gm = tile + m;
        if (gm < Nn) out[(size_t)gm * F + (i - m * F)] = sbuf[i] - lrow[m];
    }
}

// ---------------- host launcher ----------------
extern "C" void kernel_launch(void* const* d_in, const int* in_sizes, int n_in,
                              void* d_out, int out_size) {
    const float* x   = (const float*)d_in[0];
    const void*  ei  = d_in[1];
    const float* W1  = (const float*)d_in[2];
    const float* a1s = (const float*)d_in[3];
    const float* a1d = (const float*)d_in[4];
    const float* b1  = (const float*)d_in[5];
    const float* W2  = (const float*)d_in[6];
    const float* a2s = (const float*)d_in[7];
    const float* a2d = (const float*)d_in[8];
    const float* b2  = (const float*)d_in[9];
    const float* W3  = (const float*)d_in[10];
    const float* a3s = (const float*)d_in[11];
    const float* a3d = (const float*)d_in[12];
    const float* b3  = (const float*)d_in[13];
    float* out = (float*)d_out;

    float *p_aggx, *p_agg, *p_als, *p_ald;
    __half *p_hh, *p_x2h;
    int *p_counts;
    cudaGetSymbolAddress((void**)&p_aggx, g_aggx);
    cudaGetSymbolAddress((void**)&p_agg, g_agg);
    cudaGetSymbolAddress((void**)&p_hh, g_hh);
    cudaGetSymbolAddress((void**)&p_x2h, g_x2h);
    cudaGetSymbolAddress((void**)&p_als, g_als);
    cudaGetSymbolAddress((void**)&p_ald, g_ald);
    cudaGetSymbolAddress((void**)&p_counts, g_counts);

    // ---- CSR build + layer-3 weight folding ----
    detect_idx_kernel<<<1, 32>>>((const int*)ei);
    cudaMemsetAsync(p_counts, 0, N_NODES * sizeof(int));
    prep3_kernel<<<2, 256>>>(W3, a3s, a3d);
    prep_wcat_kernel<<<(384 * 40 + 255) / 256, 256>>>(W3);
    count_kernel<<<(E_TOT + 255) / 256, 256>>>(ei);
    bsum_kernel<<<SCAN_NB, SCAN_B>>>();
    bscan_kernel<<<1, SCAN_B>>>();
    offsets_kernel<<<SCAN_NB, SCAN_B>>>();
    fill_kernel<<<(E_TOT + 255) / 256, 256>>>(ei);

    const int AGG_GRID = (N_NODES * 32 + 255) / 256;

    // ---- layer 1: 128 -> 4x16 concat ----
    {
        constexpr int K = 128, F = 64, BM = 128, TM = 4, TF = 8, H = 4;
        size_t smem = (size_t)(K * F + BM * (K + 1) + BM * 2 * H) * sizeof(float);
        cudaFuncSetAttribute(gemm_al_kernel<K, F, BM, TM, TF, H>,
                             cudaFuncAttributeMaxDynamicSharedMemorySize, (int)smem);
        int grid = (N_NODES + BM - 1) / BM;
        gemm_al_kernel<K, F, BM, TM, TF, H><<<grid, (BM / TM) * (F / TF), smem>>>(
            x, W1, a1s, a1d, p_hh, p_als, p_ald, N_NODES);
        agg12_kernel<false><<<AGG_GRID, 256>>>(p_hh, p_als, p_ald, b1, p_agg);
    }

    // ---- layer 2: 64 -> 4x16 concat (output fp16 for layer-3 gather) ----
    {
        constexpr int K = 64, F = 64, BM = 128, TM = 4, TF = 8, H = 4;
        size_t smem = (size_t)(K * F + BM * (K + 1) + BM * 2 * H) * sizeof(float);
        cudaFuncSetAttribute(gemm_al_kernel<K, F, BM, TM, TF, H>,
                             cudaFuncAttributeMaxDynamicSharedMemorySize, (int)smem);
        int grid = (N_NODES + BM - 1) / BM;
        gemm_al_kernel<K, F, BM, TM, TF, H><<<grid, (BM / TM) * (F / TF), smem>>>(
            p_agg, W2, a2s, a2d, p_hh, p_als, p_ald, N_NODES);
        agg12_kernel<true><<<AGG_GRID, 256>>>(p_hh, p_als, p_ald, b2, p_x2h);
    }

    // ---- layer 3: logits from x2, aggregate x2 per head, folded GEMM + softmax ----
    logit3_kernel<<<(N_NODES + 63) / 64, 256>>>(p_x2h);
    agg3x_kernel<<<AGG_GRID, 256>>>(p_x2h, p_als, p_ald, p_aggx);
    {
        size_t smem = (size_t)(384 * 40 + 128 * 65) * sizeof(float);
        cudaFuncSetAttribute(gemm_final_kernel,
                             cudaFuncAttributeMaxDynamicSharedMemorySize, (int)smem);
        gemm_final_kernel<<<(N_NODES + 127) / 128, 256, smem>>>(p_aggx, b3, out, N_NODES);
    }
}

// round 8
// speedup vs baseline: 1.3490x; 1.1591x over previous
#include <cuda_runtime.h>
#include <cuda_fp16.h>
#include <cstdint>

// ---------------- problem constants ----------------
#define N_NODES 50000
#define N_EDGES 1600000
#define E_TOT   (N_EDGES + N_NODES)   // + self loops
#define F_IN    128

#define SCAN_B   256
#define SCAN_NB  ((N_NODES + SCAN_B - 1) / SCAN_B)   // 196

// ---------------- device scratch ----------------
__device__ __half g_aggx[(size_t)N_NODES * 384];  // layer-3 per-head aggregated x (fp16)
__device__ float  g_agg[(size_t)N_NODES * 64];    // layer-1 agg output (fp32, GEMM input)
__device__ __half g_hh[(size_t)N_NODES * 64];     // GEMM feature output (gathered), fp16
__device__ __half g_x2h[(size_t)N_NODES * 64];    // layer-2 agg output (gathered), fp16
__device__ float  g_als[(size_t)N_NODES * 6];
__device__ float  g_ald[(size_t)N_NODES * 6];
__device__ float  g_w3cat[384 * 40];              // folded W3 (head-mean included)
__device__ float  g_bs[64 * 6];
__device__ float  g_bd[64 * 6];
__device__ int    g_counts[N_NODES];
__device__ int    g_cursor[N_NODES];
__device__ int    g_offsets[N_NODES + 1];
__device__ int    g_csr[E_TOT];
__device__ int    g_bsum[SCAN_NB];
__device__ int    g_bpre[SCAN_NB];
__device__ int    g_idx64;

// ---------------- dtype detect ----------------
__global__ void detect_idx_kernel(const int* p) {
    int lane = threadIdx.x;
    int bad = 0;
    #pragma unroll
    for (int r = 0; r < 8; r++) {
        int i = lane + r * 32;
        if (p[2 * i + 1] != 0) bad = 1;
    }
    bad = __any_sync(0xffffffffu, bad);
    if (lane == 0) g_idx64 = bad ? 0 : 1;
}

__device__ __forceinline__ void load_edge(const void* ei, int i, int& src, int& dst) {
    if (i < N_EDGES) {
        if (g_idx64) {
            const long long* q = (const long long*)ei;
            src = (int)q[i];
            dst = (int)q[(size_t)N_EDGES + i];
        } else {
            const int* q = (const int*)ei;
            src = q[i];
            dst = q[N_EDGES + i];
        }
    } else {
        src = dst = i - N_EDGES;  // self loop
    }
}

__global__ void count_kernel(const void* ei) {
    int i = blockIdx.x * blockDim.x + threadIdx.x;
    if (i >= E_TOT) return;
    int src, dst;
    load_edge(ei, i, src, dst);
    atomicAdd(&g_counts[dst], 1);
}

// ---------------- 3-stage parallel exclusive scan ----------------
__global__ void bsum_kernel() {
    int b = blockIdx.x, t = threadIdx.x;
    int idx = b * SCAN_B + t;
    int v = (idx < N_NODES) ? g_counts[idx] : 0;
    #pragma unroll
    for (int o = 16; o > 0; o >>= 1) v += __shfl_xor_sync(0xffffffffu, v, o);
    __shared__ int ws[SCAN_B / 32];
    if ((t & 31) == 0) ws[t >> 5] = v;
    __syncthreads();
    if (t < SCAN_B / 32) {
        int s = ws[t];
        #pragma unroll
        for (int o = SCAN_B / 64; o > 0; o >>= 1) s += __shfl_xor_sync(0xffu, s, o);
        if (t == 0) g_bsum[b] = s;
    }
}

__global__ void bscan_kernel() {
    __shared__ int sm[SCAN_B];
    int t = threadIdx.x;
    int v = (t < SCAN_NB) ? g_bsum[t] : 0;
    sm[t] = v;
    __syncthreads();
    #pragma unroll
    for (int off = 1; off < SCAN_B; off <<= 1) {
        int u = (t >= off) ? sm[t - off] : 0;
        __syncthreads();
        sm[t] += u;
        __syncthreads();
    }
    if (t < SCAN_NB) g_bpre[t] = sm[t] - v;
}

__global__ void offsets_kernel() {
    __shared__ int sm[SCAN_B];
    int b = blockIdx.x, t = threadIdx.x;
    int idx = b * SCAN_B + t;
    int v = (idx < N_NODES) ? g_counts[idx] : 0;
    sm[t] = v;
    __syncthreads();
    #pragma unroll
    for (int off = 1; off < SCAN_B; off <<= 1) {
        int u = (t >= off) ? sm[t - off] : 0;
        __syncthreads();
        sm[t] += u;
        __syncthreads();
    }
    int excl = sm[t] - v + g_bpre[b];
    if (idx < N_NODES) {
        g_offsets[idx] = excl;
        g_cursor[idx] = excl;
    }
    if (idx == 0) g_offsets[N_NODES] = E_TOT;
}

__global__ void fill_kernel(const void* ei) {
    int i = blockIdx.x * blockDim.x + threadIdx.x;
    if (i >= E_TOT) return;
    int src, dst;
    load_edge(ei, i, src, dst);
    int pos = atomicAdd(&g_cursor[dst], 1);
    g_csr[pos] = src;
}

// ---------------- layer-3 prep ----------------
__global__ void prep3_kernel(const float* __restrict__ W3, const float* __restrict__ a3s,
                             const float* __restrict__ a3d) {
    int t = blockIdx.x * blockDim.x + threadIdx.x;
    if (t >= 384) return;
    int k = t / 6, h = t % 6;
    float ss = 0.f, sd = 0.f;
    #pragma unroll
    for (int c = 0; c < 40; c++) {
        float w = W3[k * 240 + h * 40 + c];
        ss += w * a3s[h * 40 + c];
        sd += w * a3d[h * 40 + c];
    }
    g_bs[k * 6 + h] = ss;
    g_bd[k * 6 + h] = sd;
}

__global__ void prep_wcat_kernel(const float* __restrict__ W3) {
    int i = blockIdx.x * blockDim.x + threadIdx.x;
    if (i >= 384 * 40) return;
    int hk = i / 40, c = i % 40;
    int h = hk >> 6, k = hk & 63;
    g_w3cat[i] = W3[k * 240 + h * 40 + c] * (1.f / 6.f);
}

// als/ald[n, 0..5] = x[n,:] @ Bs / Bd   (x is layer-2 output, fp16)
__global__ void logit3_kernel(const __half* __restrict__ X) {
    __shared__ float xs[64 * 65];
    __shared__ float Bsm[64 * 12];
    int tid = threadIdx.x;
    int n0 = blockIdx.x * 64;
    for (int i = tid; i < 768; i += 256) {
        int k = i / 12, j = i % 12;
        Bsm[k * 12 + j] = (j < 6) ? g_bs[k * 6 + j] : g_bd[k * 6 + (j - 6)];
    }
    for (int i = tid; i < 64 * 32; i += 256) {
        int m = i >> 5, k2 = (i & 31) * 2;
        int gm = n0 + m;
        float2 v = make_float2(0.f, 0.f);
        if (gm < N_NODES)
            v = __half22float2(*reinterpret_cast<const __half2*>(&X[(size_t)gm * 64 + k2]));
        xs[m * 65 + k2] = v.x;
        xs[m * 65 + k2 + 1] = v.y;
    }
    __syncthreads();
    for (int p = tid; p < 768; p += 256) {
        int m = p / 12, j = p % 12;
        float s = 0.f;
        #pragma unroll
        for (int k = 0; k < 64; k++) s = fmaf(xs[m * 65 + k], Bsm[k * 12 + j], s);
        int gm = n0 + m;
        if (gm < N_NODES) {
            if (j < 6) g_als[gm * 6 + j] = s;
            else       g_ald[gm * 6 + (j - 6)] = s;
        }
    }
}

// ---------------- fused GEMM + attention-logit kernel (layers 1,2) ----------------
template <int K, int F, int BM, int TM, int TF, int H>
__global__ void gemm_al_kernel(const float* __restrict__ X, const float* __restrict__ W,
                               const float* __restrict__ Avs, const float* __restrict__ Avd,
                               __half* __restrict__ Ho, float* __restrict__ als,
                               float* __restrict__ ald, int Nn) {
    constexpr int MTH = BM / TM;
    constexpr int FTH = F / TF;
    constexpr int NTH = MTH * FTH;
    constexpr int C = F / H;
    constexpr int XLD = K + 1;
    extern __shared__ float sh[];
    float* ws = sh;
    float* xs = ws + K * F;
    float* asum = xs + BM * XLD;

    int tid = threadIdx.x;
    for (int i = tid; i < K * F; i += NTH) ws[i] = W[i];

    int mx = tid % MTH;
    int fx = tid / MTH;
    int f0 = fx * TF;
    int headT = f0 / C;
    float ras[TF], rad[TF];
    #pragma unroll
    for (int j = 0; j < TF; j++) { ras[j] = Avs[f0 + j]; rad[j] = Avd[f0 + j]; }

    int tile = blockIdx.x * BM;
    __syncthreads();
    for (int i = tid; i < BM * K; i += NTH) {
        int m = i / K, k = i - m * K;
        int gm = tile + m;
        xs[m * XLD + k] = (gm < Nn) ? X[(size_t)gm * K + k] : 0.f;
    }
    for (int i = tid; i < BM * 2 * H; i += NTH) asum[i] = 0.f;
    __syncthreads();

    float acc[TM][TF];
    #pragma unroll
    for (int i = 0; i < TM; i++)
        #pragma unroll
        for (int j = 0; j < TF; j++) acc[i][j] = 0.f;

    #pragma unroll 4
    for (int k = 0; k < K; k++) {
        float xv[TM];
        #pragma unroll
        for (int i = 0; i < TM; i++) xv[i] = xs[(mx + i * MTH) * XLD + k];
        float wv[TF];
        #pragma unroll
        for (int j4 = 0; j4 < TF / 4; j4++) {
            float4 w4 = *reinterpret_cast<const float4*>(&ws[k * F + f0 + j4 * 4]);
            wv[j4 * 4 + 0] = w4.x; wv[j4 * 4 + 1] = w4.y;
            wv[j4 * 4 + 2] = w4.z; wv[j4 * 4 + 3] = w4.w;
        }
        #pragma unroll
        for (int i = 0; i < TM; i++)
            #pragma unroll
            for (int j = 0; j < TF; j++) acc[i][j] = fmaf(xv[i], wv[j], acc[i][j]);
    }

    #pragma unroll
    for (int i = 0; i < TM; i++) {
        int m = mx + i * MTH;
        int gm = tile + m;
        if (gm < Nn) {
            __half2 p[TF / 2];
            #pragma unroll
            for (int q = 0; q < TF / 2; q++)
                p[q] = __floats2half2_rn(acc[i][2 * q], acc[i][2 * q + 1]);
            uint4 u;
            u.x = *reinterpret_cast<unsigned*>(&p[0]);
            u.y = *reinterpret_cast<unsigned*>(&p[1]);
            u.z = *reinterpret_cast<unsigned*>(&p[2]);
            u.w = *reinterpret_cast<unsigned*>(&p[3]);
            *reinterpret_cast<uint4*>(&Ho[(size_t)gm * F + f0]) = u;

            float ss = 0.f, sd = 0.f;
            #pragma unroll
            for (int j = 0; j < TF; j++) {
                ss += acc[i][j] * ras[j];
                sd += acc[i][j] * rad[j];
            }
            atomicAdd(&asum[m * 2 * H + headT], ss);
            atomicAdd(&asum[m * 2 * H + H + headT], sd);
        }
    }
    __syncthreads();
    for (int i = tid; i < BM * H; i += NTH) {
        int m = i / H, hh = i - m * H;
        int gm = tile + m;
        if (gm < Nn) {
            als[gm * H + hh] = asum[m * 2 * H + hh];
            ald[gm * H + hh] = asum[m * 2 * H + H + hh];
        }
    }
}

// ---------------- layers 1/2 aggregation: chunk-staged, one warp per node ----------------
// Per 32-edge chunk: lane loads ONE csr entry + ONE als float4, computes 4 exp
// weights, stages {src, w[4]} to smem. Gather loop then reads via broadcast LDS:
// all h-gathers in a chunk are independent -> high MLP, ~8 inst/edge.
template <bool OUT_HALF>
__global__ void agg12_kernel(const __half* __restrict__ h, const float* __restrict__ als,
                             const float* __restrict__ ald, const float* __restrict__ bias,
                             void* __restrict__ outv) {
    __shared__ int   ssm[8][32];
    __shared__ float wsm[8][32][4];
    int gw = (blockIdx.x * blockDim.x + threadIdx.x) >> 5;
    if (gw >= N_NODES) return;
    int lane = threadIdx.x & 31;
    int wi = (threadIdx.x >> 5) & 7;
    int beg = g_offsets[gw], end = g_offsets[gw + 1];

    float4 at = *reinterpret_cast<const float4*>(&ald[gw * 4]);
    float aldh[4] = {at.x, at.y, at.z, at.w};

    int ch = lane * 2;
    int hr = ch >> 4;  // head 0..3
    float2 acc = make_float2(0.f, 0.f);
    float sv[4] = {0.f, 0.f, 0.f, 0.f};

    for (int base = beg; base < end; base += 32) {
        int i = base + lane;
        int sreg = 0;
        float w[4] = {0.f, 0.f, 0.f, 0.f};
        if (i < end) {
            sreg = g_csr[i];
            float4 t = __ldg(reinterpret_cast<const float4*>(&als[sreg * 4]));
            float av[4] = {t.x, t.y, t.z, t.w};
            #pragma unroll
            for (int hh = 0; hh < 4; hh++) {
                float e = av[hh] + aldh[hh];
                e = e > 0.f ? e : 0.2f * e;
                w[hh] = __expf(e);
                sv[hh] += w[hh];
            }
        }
        ssm[wi][lane] = sreg;
        *reinterpret_cast<float4*>(&wsm[wi][lane][0]) = make_float4(w[0], w[1], w[2], w[3]);
        __syncwarp();
        int cnt = min(32, end - base);
        #pragma unroll 4
        for (int j = 0; j < cnt; j++) {
            int s = ssm[wi][j];
            float wv = wsm[wi][j][hr];
            float2 hv = __half22float2(
                *reinterpret_cast<const __half2*>(&h[(size_t)s * 64 + ch]));
            acc.x = fmaf(wv, hv.x, acc.x);
            acc.y = fmaf(wv, hv.y, acc.y);
        }
        __syncwarp();
    }

    // reduce denominators (each lane holds partial sums of all 4 heads)
    #pragma unroll
    for (int hh = 0; hh < 4; hh++)
        #pragma unroll
        for (int o = 16; o > 0; o >>= 1)
            sv[hh] += __shfl_xor_sync(0xffffffffu, sv[hh], o);

    float inv = 1.f / sv[hr];
    float vx = acc.x * inv + bias[ch];
    float vy = acc.y * inv + bias[ch + 1];
    vx = vx > 0.f ? vx : (__expf(vx) - 1.f);
    vy = vy > 0.f ? vy : (__expf(vy) - 1.f);
    if (OUT_HALF) {
        *reinterpret_cast<__half2*>(&((__half*)outv)[(size_t)gw * 64 + ch]) =
            __floats2half2_rn(vx, vy);
    } else {
        *reinterpret_cast<float2*>(&((float*)outv)[(size_t)gw * 64 + ch]) =
            make_float2(vx, vy);
    }
}

// ---------------- layer-3 aggregation: shfl-staged weights, fp16 in/out ----------------
__global__ void agg3x_kernel(const __half* __restrict__ x, const float* __restrict__ als,
                             const float* __restrict__ ald, __half* __restrict__ aggx) {
    int gw = (blockIdx.x * blockDim.x + threadIdx.x) >> 5;
    if (gw >= N_NODES) return;
    int lane = threadIdx.x & 31;
    int beg = g_offsets[gw], end = g_offsets[gw + 1];

    float aldh[6];
    #pragma unroll
    for (int q = 0; q < 3; q++) {
        float2 t = *reinterpret_cast<const float2*>(&ald[gw * 6 + 2 * q]);
        aldh[2 * q] = t.x; aldh[2 * q + 1] = t.y;
    }

    int ch = lane * 2;
    float2 acc[6];
    float sv[6];
    #pragma unroll
    for (int hh = 0; hh < 6; hh++) { acc[hh] = make_float2(0.f, 0.f); sv[hh] = 0.f; }

    for (int base = beg; base < end; base += 32) {
        int i = base + lane;
        int sreg = 0;
        float w[6];
        #pragma unroll
        for (int hh = 0; hh < 6; hh++) w[hh] = 0.f;
        if (i < end) {
            sreg = g_csr[i];
            #pragma unroll
            for (int q = 0; q < 3; q++) {
                float2 t = __ldg(reinterpret_cast<const float2*>(&als[sreg * 6 + 2 * q]));
                float e0 = t.x + aldh[2 * q];
                float e1 = t.y + aldh[2 * q + 1];
                e0 = e0 > 0.f ? e0 : 0.2f * e0;
                e1 = e1 > 0.f ? e1 : 0.2f * e1;
                w[2 * q] = __expf(e0);
                w[2 * q + 1] = __expf(e1);
            }
            #pragma unroll
            for (int hh = 0; hh < 6; hh++) sv[hh] += w[hh];
        }
        int cnt = min(32, end - base);
        for (int j = 0; j < cnt; j++) {
            int s = __shfl_sync(0xffffffffu, sreg, j);
            float w0 = __shfl_sync(0xffffffffu, w[0], j);
            float w1 = __shfl_sync(0xffffffffu, w[1], j);
            float w2 = __shfl_sync(0xffffffffu, w[2], j);
            float w3 = __shfl_sync(0xffffffffu, w[3], j);
            float w4 = __shfl_sync(0xffffffffu, w[4], j);
            float w5 = __shfl_sync(0xffffffffu, w[5], j);
            float2 hv = __half22float2(
                *reinterpret_cast<const __half2*>(&x[(size_t)s * 64 + ch]));
            acc[0].x = fmaf(w0, hv.x, acc[0].x); acc[0].y = fmaf(w0, hv.y, acc[0].y);
            acc[1].x = fmaf(w1, hv.x, acc[1].x); acc[1].y = fmaf(w1, hv.y, acc[1].y);
            acc[2].x = fmaf(w2, hv.x, acc[2].x); acc[2].y = fmaf(w2, hv.y, acc[2].y);
            acc[3].x = fmaf(w3, hv.x, acc[3].x); acc[3].y = fmaf(w3, hv.y, acc[3].y);
            acc[4].x = fmaf(w4, hv.x, acc[4].x); acc[4].y = fmaf(w4, hv.y, acc[4].y);
            acc[5].x = fmaf(w5, hv.x, acc[5].x); acc[5].y = fmaf(w5, hv.y, acc[5].y);
        }
    }

    #pragma unroll
    for (int hh = 0; hh < 6; hh++)
        #pragma unroll
        for (int o = 16; o > 0; o >>= 1)
            sv[hh] += __shfl_xor_sync(0xffffffffu, sv[hh], o);

    size_t b2 = (size_t)gw * 384;
    #pragma unroll
    for (int hh = 0; hh < 6; hh++) {
        float inv = 1.f / sv[hh];
        *reinterpret_cast<__half2*>(&aggx[b2 + hh * 64 + ch]) =
            __floats2half2_rn(acc[hh].x * inv, acc[hh].y * inv);
    }
}

// ---------------- final GEMM: fp16 [N,384] @ Wcat[384,40] + bias + elu + log_softmax ----------------
__global__ void gemm_final_kernel(const __half* __restrict__ X, const float* __restrict__ b3,
                                  float* __restrict__ out, int Nn) {
    constexpr int BM = 128, BK = 64, Ktot = 384, F = 40;
    constexpr int TM = 4, TF = 5, MTH = 32, NTH = 256;
    extern __shared__ float sh[];
    float* ws = sh;              // 384*40
    float* xs = ws + Ktot * F;   // BM*(BK+1)

    int tid = threadIdx.x;
    for (int i = tid; i < Ktot * F; i += NTH) ws[i] = g_w3cat[i];

    int mx = tid % MTH;
    int fx = tid / MTH;
    int f0 = fx * TF;
    int tile = blockIdx.x * BM;

    float acc[TM][TF];
    #pragma unroll
    for (int i = 0; i < TM; i++)
        #pragma unroll
        for (int j = 0; j < TF; j++) acc[i][j] = 0.f;

    for (int kt = 0; kt < Ktot; kt += BK) {
        __syncthreads();
        for (int i = tid; i < BM * BK / 2; i += NTH) {
            int m = i / (BK / 2), k2 = (i % (BK / 2)) * 2;
            int gm = tile + m;
            float2 v = make_float2(0.f, 0.f);
            if (gm < Nn)
                v = __half22float2(*reinterpret_cast<const __half2*>(
                    &X[(size_t)gm * Ktot + kt + k2]));
            xs[m * (BK + 1) + k2] = v.x;
            xs[m * (BK + 1) + k2 + 1] = v.y;
        }
        __syncthreads();
        #pragma unroll 4
        for (int k = 0; k < BK; k++) {
            float xv[TM];
            #pragma unroll
            for (int i = 0; i < TM; i++) xv[i] = xs[(mx + i * MTH) * (BK + 1) + k];
            float wv[TF];
            #pragma unroll
            for (int j = 0; j < TF; j++) wv[j] = ws[(kt + k) * F + f0 + j];
            #pragma unroll
            for (int i = 0; i < TM; i++)
                #pragma unroll
                for (int j = 0; j < TF; j++) acc[i][j] = fmaf(xv[i], wv[j], acc[i][j]);
        }
    }

    __syncthreads();
    float* sbuf = xs;              // BM*40
    float* lrow = xs + BM * F;     // BM
    #pragma unroll
    for (int i = 0; i < TM; i++) {
        int m = mx + i * MTH;
        #pragma unroll
        for (int j = 0; j < TF; j++)
            sbuf[m * F + f0 + j] = acc[i][j] + b3[f0 + j];
    }
    __syncthreads();
    if (tid < BM) {
        int m = tid;
        float mxv = -1e30f;
        #pragma unroll 4
        for (int c = 0; c < F; c++) {
            float v = sbuf[m * F + c];
            v = v > 0.f ? v : (__expf(v) - 1.f);
            sbuf[m * F + c] = v;
            mxv = fmaxf(mxv, v);
        }
        float se = 0.f;
        #pragma unroll 4
        for (int c = 0; c < F; c++) se += __expf(sbuf[m * F + c] - mxv);
        lrow[m] = __logf(se) + mxv;
    }
    __syncthreads();
    for (int i = tid; i < BM * F; i += NTH) {
        int m = i / F;
        int gm = tile + m;
        if (gm < Nn) out[(size_t)gm * F + (i - m * F)] = sbuf[i] - lrow[m];
    }
}

// ---------------- host launcher ----------------
extern "C" void kernel_launch(void* const* d_in, const int* in_sizes, int n_in,
                              void* d_out, int out_size) {
    const float* x   = (const float*)d_in[0];
    const void*  ei  = d_in[1];
    const float* W1  = (const float*)d_in[2];
    const float* a1s = (const float*)d_in[3];
    const float* a1d = (const float*)d_in[4];
    const float* b1  = (const float*)d_in[5];
    const float* W2  = (const float*)d_in[6];
    const float* a2s = (const float*)d_in[7];
    const float* a2d = (const float*)d_in[8];
    const float* b2  = (const float*)d_in[9];
    const float* W3  = (const float*)d_in[10];
    const float* a3s = (const float*)d_in[11];
    const float* a3d = (const float*)d_in[12];
    const float* b3  = (const float*)d_in[13];
    float* out = (float*)d_out;

    float *p_agg, *p_als, *p_ald;
    __half *p_aggx, *p_hh, *p_x2h;
    int *p_counts;
    cudaGetSymbolAddress((void**)&p_aggx, g_aggx);
    cudaGetSymbolAddress((void**)&p_agg, g_agg);
    cudaGetSymbolAddress((void**)&p_hh, g_hh);
    cudaGetSymbolAddress((void**)&p_x2h, g_x2h);
    cudaGetSymbolAddress((void**)&p_als, g_als);
    cudaGetSymbolAddress((void**)&p_ald, g_ald);
    cudaGetSymbolAddress((void**)&p_counts, g_counts);

    // ---- CSR build + layer-3 weight folding ----
    detect_idx_kernel<<<1, 32>>>((const int*)ei);
    cudaMemsetAsync(p_counts, 0, N_NODES * sizeof(int));
    prep3_kernel<<<2, 256>>>(W3, a3s, a3d);
    prep_wcat_kernel<<<(384 * 40 + 255) / 256, 256>>>(W3);
    count_kernel<<<(E_TOT + 255) / 256, 256>>>(ei);
    bsum_kernel<<<SCAN_NB, SCAN_B>>>();
    bscan_kernel<<<1, SCAN_B>>>();
    offsets_kernel<<<SCAN_NB, SCAN_B>>>();
    fill_kernel<<<(E_TOT + 255) / 256, 256>>>(ei);

    const int AGG_GRID = (N_NODES * 32 + 255) / 256;

    // ---- layer 1: 128 -> 4x16 concat ----
    {
        constexpr int K = 128, F = 64, BM = 128, TM = 4, TF = 8, H = 4;
        size_t smem = (size_t)(K * F + BM * (K + 1) + BM * 2 * H) * sizeof(float);
        cudaFuncSetAttribute(gemm_al_kernel<K, F, BM, TM, TF, H>,
                             cudaFuncAttributeMaxDynamicSharedMemorySize, (int)smem);
        int grid = (N_NODES + BM - 1) / BM;
        gemm_al_kernel<K, F, BM, TM, TF, H><<<grid, (BM / TM) * (F / TF), smem>>>(
            x, W1, a1s, a1d, p_hh, p_als, p_ald, N_NODES);
        agg12_kernel<false><<<AGG_GRID, 256>>>(p_hh, p_als, p_ald, b1, p_agg);
    }

    // ---- layer 2: 64 -> 4x16 concat (output fp16 for layer-3 gather) ----
    {
        constexpr int K = 64, F = 64, BM = 128, TM = 4, TF = 8, H = 4;
        size_t smem = (size_t)(K * F + BM * (K + 1) + BM * 2 * H) * sizeof(float);
        cudaFuncSetAttribute(gemm_al_kernel<K, F, BM, TM, TF, H>,
                             cudaFuncAttributeMaxDynamicSharedMemorySize, (int)smem);
        int grid = (N_NODES + BM - 1) / BM;
        gemm_al_kernel<K, F, BM, TM, TF, H><<<grid, (BM / TM) * (F / TF), smem>>>(
            p_agg, W2, a2s, a2d, p_hh, p_als, p_ald, N_NODES);
        agg12_kernel<true><<<AGG_GRID, 256>>>(p_hh, p_als, p_ald, b2, p_x2h);
    }

    // ---- layer 3: logits from x2, aggregate x2 per head, folded GEMM + softmax ----
    logit3_kernel<<<(N_NODES + 63) / 64, 256>>>(p_x2h);
    agg3x_kernel<<<AGG_GRID, 256>>>(p_x2h, p_als, p_ald, p_aggx);
    {
        size_t smem = (size_t)(384 * 40 + 128 * 65) * sizeof(float);
        cudaFuncSetAttribute(gemm_final_kernel,
                             cudaFuncAttributeMaxDynamicSharedMemorySize, (int)smem);
        gemm_final_kernel<<<(N_NODES + 127) / 128, 256, smem>>>(p_aggx, b3, out, N_NODES);
    }
}

// round 11
// speedup vs baseline: 1.5113x; 1.1203x over previous
#include <cuda_runtime.h>
#include <cuda_fp16.h>
#include <mma.h>
#include <cstdint>

using namespace nvcuda;

// ---------------- problem constants ----------------
#define N_NODES 50000
#define N_PAD   50048   // padded to multiple of 128 for wmma tiles
#define N_EDGES 1600000
#define E_TOT   (N_EDGES + N_NODES)   // + self loops
#define F_IN    128

#define SCAN_B   256
#define SCAN_NB  ((N_NODES + SCAN_B - 1) / SCAN_B)   // 196

// ---------------- device scratch ----------------
__device__ __half g_aggx[(size_t)N_PAD * 384];    // layer-3 per-head aggregated x (fp16)
__device__ float  g_agg[(size_t)N_NODES * 64];    // layer-1 agg output (fp32, GEMM input)
__device__ __half g_hh[(size_t)N_NODES * 64];     // GEMM feature output (gathered), fp16
__device__ __half g_x2h[(size_t)N_NODES * 64];    // layer-2 agg output (gathered), fp16
__device__ float  g_als[(size_t)N_NODES * 6];
__device__ float  g_ald[(size_t)N_NODES * 6];
__device__ __half g_w3h[384 * 48];                // folded W3, fp16, padded to 48 cols
__device__ float  g_bs[64 * 6];
__device__ float  g_bd[64 * 6];
__device__ int    g_counts[N_NODES];
__device__ int    g_cursor[N_NODES];
__device__ int    g_offsets[N_NODES + 1];
__device__ int    g_csr[E_TOT];
__device__ int    g_bsum[SCAN_NB];
__device__ int    g_bpre[SCAN_NB];
__device__ int    g_idx64;

// ---------------- dtype detect ----------------
__global__ void detect_idx_kernel(const int* p) {
    int lane = threadIdx.x;
    int bad = 0;
    #pragma unroll
    for (int r = 0; r < 8; r++) {
        int i = lane + r * 32;
        if (p[2 * i + 1] != 0) bad = 1;
    }
    bad = __any_sync(0xffffffffu, bad);
    if (lane == 0) g_idx64 = bad ? 0 : 1;
}

__device__ __forceinline__ void load_edge(const void* ei, int i, int& src, int& dst) {
    if (i < N_EDGES) {
        if (g_idx64) {
            const long long* q = (const long long*)ei;
            src = (int)q[i];
            dst = (int)q[(size_t)N_EDGES + i];
        } else {
            const int* q = (const int*)ei;
            src = q[i];
            dst = q[N_EDGES + i];
        }
    } else {
        src = dst = i - N_EDGES;  // self loop
    }
}

__global__ void count_kernel(const void* ei) {
    int i = blockIdx.x * blockDim.x + threadIdx.x;
    if (i >= E_TOT) return;
    int src, dst;
    load_edge(ei, i, src, dst);
    atomicAdd(&g_counts[dst], 1);
}

// ---------------- 3-stage parallel exclusive scan ----------------
__global__ void bsum_kernel() {
    int b = blockIdx.x, t = threadIdx.x;
    int idx = b * SCAN_B + t;
    int v = (idx < N_NODES) ? g_counts[idx] : 0;
    #pragma unroll
    for (int o = 16; o > 0; o >>= 1) v += __shfl_xor_sync(0xffffffffu, v, o);
    __shared__ int ws[SCAN_B / 32];
    if ((t & 31) == 0) ws[t >> 5] = v;
    __syncthreads();
    if (t < SCAN_B / 32) {
        int s = ws[t];
        #pragma unroll
        for (int o = SCAN_B / 64; o > 0; o >>= 1) s += __shfl_xor_sync(0xffu, s, o);
        if (t == 0) g_bsum[b] = s;
    }
}

__global__ void bscan_kernel() {
    __shared__ int sm[SCAN_B];
    int t = threadIdx.x;
    int v = (t < SCAN_NB) ? g_bsum[t] : 0;
    sm[t] = v;
    __syncthreads();
    #pragma unroll
    for (int off = 1; off < SCAN_B; off <<= 1) {
        int u = (t >= off) ? sm[t - off] : 0;
        __syncthreads();
        sm[t] += u;
        __syncthreads();
    }
    if (t < SCAN_NB) g_bpre[t] = sm[t] - v;
}

__global__ void offsets_kernel() {
    __shared__ int sm[SCAN_B];
    int b = blockIdx.x, t = threadIdx.x;
    int idx = b * SCAN_B + t;
    int v = (idx < N_NODES) ? g_counts[idx] : 0;
    sm[t] = v;
    __syncthreads();
    #pragma unroll
    for (int off = 1; off < SCAN_B; off <<= 1) {
        int u = (t >= off) ? sm[t - off] : 0;
        __syncthreads();
        sm[t] += u;
        __syncthreads();
    }
    int excl = sm[t] - v + g_bpre[b];
    if (idx < N_NODES) {
        g_offsets[idx] = excl;
        g_cursor[idx] = excl;
    }
    if (idx == 0) g_offsets[N_NODES] = E_TOT;
}

__global__ void fill_kernel(const void* ei) {
    int i = blockIdx.x * blockDim.x + threadIdx.x;
    if (i >= E_TOT) return;
    int src, dst;
    load_edge(ei, i, src, dst);
    int pos = atomicAdd(&g_cursor[dst], 1);
    g_csr[pos] = src;
}

// ---------------- layer-3 prep: fold attention vecs + head-mean into W3 (fp16) ----------------
// thread t < 384: Bs/Bd; all threads: g_w3h[384*48] (cols 40..47 zero)
__global__ void prep3_kernel(const float* __restrict__ W3, const float* __restrict__ a3s,
                             const float* __restrict__ a3d) {
    int t = blockIdx.x * blockDim.x + threadIdx.x;
    if (t < 384) {
        int k = t / 6, h = t % 6;
        float ss = 0.f, sd = 0.f;
        #pragma unroll
        for (int c = 0; c < 40; c++) {
            float w = W3[k * 240 + h * 40 + c];
            ss += w * a3s[h * 40 + c];
            sd += w * a3d[h * 40 + c];
        }
        g_bs[k * 6 + h] = ss;
        g_bd[k * 6 + h] = sd;
    }
    if (t < 384 * 48) {
        int hk = t / 48, c = t % 48;
        int h = hk >> 6, k = hk & 63;
        float v = (c < 40) ? W3[k * 240 + h * 40 + c] * (1.f / 6.f) : 0.f;
        g_w3h[t] = __float2half(v);
    }
}

// als/ald[n, 0..5] = x[n,:] @ Bs / Bd   (x is layer-2 output, fp16)
__global__ void logit3_kernel(const __half* __restrict__ X) {
    __shared__ float xs[64 * 65];
    __shared__ float Bsm[64 * 12];
    int tid = threadIdx.x;
    int n0 = blockIdx.x * 64;
    for (int i = tid; i < 768; i += 256) {
        int k = i / 12, j = i % 12;
        Bsm[k * 12 + j] = (j < 6) ? g_bs[k * 6 + j] : g_bd[k * 6 + (j - 6)];
    }
    for (int i = tid; i < 64 * 32; i += 256) {
        int m = i >> 5, k2 = (i & 31) * 2;
        int gm = n0 + m;
        float2 v = make_float2(0.f, 0.f);
        if (gm < N_NODES)
            v = __half22float2(*reinterpret_cast<const __half2*>(&X[(size_t)gm * 64 + k2]));
        xs[m * 65 + k2] = v.x;
        xs[m * 65 + k2 + 1] = v.y;
    }
    __syncthreads();
    for (int p = tid; p < 768; p += 256) {
        int m = p / 12, j = p % 12;
        float s = 0.f;
        #pragma unroll
        for (int k = 0; k < 64; k++) s = fmaf(xs[m * 65 + k], Bsm[k * 12 + j], s);
        int gm = n0 + m;
        if (gm < N_NODES) {
            if (j < 6) g_als[gm * 6 + j] = s;
            else       g_ald[gm * 6 + (j - 6)] = s;
        }
    }
}

// ---------------- fused GEMM + attention-logit kernel (layers 1,2) ----------------
template <int K, int F, int BM, int TM, int TF, int H>
__global__ void gemm_al_kernel(const float* __restrict__ X, const float* __restrict__ W,
                               const float* __restrict__ Avs, const float* __restrict__ Avd,
                               __half* __restrict__ Ho, float* __restrict__ als,
                               float* __restrict__ ald, int Nn) {
    constexpr int MTH = BM / TM;
    constexpr int FTH = F / TF;
    constexpr int NTH = MTH * FTH;
    constexpr int C = F / H;
    constexpr int XLD = K + 1;
    extern __shared__ float sh[];
    float* ws = sh;
    float* xs = ws + K * F;
    float* asum = xs + BM * XLD;

    int tid = threadIdx.x;
    for (int i = tid; i < K * F; i += NTH) ws[i] = W[i];

    int mx = tid % MTH;
    int fx = tid / MTH;
    int f0 = fx * TF;
    int headT = f0 / C;
    float ras[TF], rad[TF];
    #pragma unroll
    for (int j = 0; j < TF; j++) { ras[j] = Avs[f0 + j]; rad[j] = Avd[f0 + j]; }

    int tile = blockIdx.x * BM;
    __syncthreads();
    for (int i = tid; i < BM * K; i += NTH) {
        int m = i / K, k = i - m * K;
        int gm = tile + m;
        xs[m * XLD + k] = (gm < Nn) ? X[(size_t)gm * K + k] : 0.f;
    }
    for (int i = tid; i < BM * 2 * H; i += NTH) asum[i] = 0.f;
    __syncthreads();

    float acc[TM][TF];
    #pragma unroll
    for (int i = 0; i < TM; i++)
        #pragma unroll
        for (int j = 0; j < TF; j++) acc[i][j] = 0.f;

    #pragma unroll 4
    for (int k = 0; k < K; k++) {
        float xv[TM];
        #pragma unroll
        for (int i = 0; i < TM; i++) xv[i] = xs[(mx + i * MTH) * XLD + k];
        float wv[TF];
        #pragma unroll
        for (int j4 = 0; j4 < TF / 4; j4++) {
            float4 w4 = *reinterpret_cast<const float4*>(&ws[k * F + f0 + j4 * 4]);
            wv[j4 * 4 + 0] = w4.x; wv[j4 * 4 + 1] = w4.y;
            wv[j4 * 4 + 2] = w4.z; wv[j4 * 4 + 3] = w4.w;
        }
        #pragma unroll
        for (int i = 0; i < TM; i++)
            #pragma unroll
            for (int j = 0; j < TF; j++) acc[i][j] = fmaf(xv[i], wv[j], acc[i][j]);
    }

    #pragma unroll
    for (int i = 0; i < TM; i++) {
        int m = mx + i * MTH;
        int gm = tile + m;
        if (gm < Nn) {
            __half2 p[TF / 2];
            #pragma unroll
            for (int q = 0; q < TF / 2; q++)
                p[q] = __floats2half2_rn(acc[i][2 * q], acc[i][2 * q + 1]);
            uint4 u;
            u.x = *reinterpret_cast<unsigned*>(&p[0]);
            u.y = *reinterpret_cast<unsigned*>(&p[1]);
            u.z = *reinterpret_cast<unsigned*>(&p[2]);
            u.w = *reinterpret_cast<unsigned*>(&p[3]);
            *reinterpret_cast<uint4*>(&Ho[(size_t)gm * F + f0]) = u;

            float ss = 0.f, sd = 0.f;
            #pragma unroll
            for (int j = 0; j < TF; j++) {
                ss += acc[i][j] * ras[j];
                sd += acc[i][j] * rad[j];
            }
            atomicAdd(&asum[m * 2 * H + headT], ss);
            atomicAdd(&asum[m * 2 * H + H + headT], sd);
        }
    }
    __syncthreads();
    for (int i = tid; i < BM * H; i += NTH) {
        int m = i / H, hh = i - m * H;
        int gm = tile + m;
        if (gm < Nn) {
            als[gm * H + hh] = asum[m * 2 * H + hh];
            ald[gm * H + hh] = asum[m * 2 * H + H + hh];
        }
    }
}

// ---------------- layers 1/2 aggregation: chunk-staged, one warp per node ----------------
template <bool OUT_HALF>
__global__ void agg12_kernel(const __half* __restrict__ h, const float* __restrict__ als,
                             const float* __restrict__ ald, const float* __restrict__ bias,
                             void* __restrict__ outv) {
    __shared__ int   ssm[8][32];
    __shared__ float wsm[8][32][4];
    int gw = (blockIdx.x * blockDim.x + threadIdx.x) >> 5;
    if (gw >= N_NODES) return;
    int lane = threadIdx.x & 31;
    int wi = (threadIdx.x >> 5) & 7;
    int beg = g_offsets[gw], end = g_offsets[gw + 1];

    float4 at = *reinterpret_cast<const float4*>(&ald[gw * 4]);
    float aldh[4] = {at.x, at.y, at.z, at.w};

    int ch = lane * 2;
    int hr = ch >> 4;  // head 0..3
    float2 acc = make_float2(0.f, 0.f);
    float sv[4] = {0.f, 0.f, 0.f, 0.f};

    for (int base = beg; base < end; base += 32) {
        int i = base + lane;
        int sreg = 0;
        float w[4] = {0.f, 0.f, 0.f, 0.f};
        if (i < end) {
            sreg = g_csr[i];
            float4 t = __ldg(reinterpret_cast<const float4*>(&als[sreg * 4]));
            float av[4] = {t.x, t.y, t.z, t.w};
            #pragma unroll
            for (int hh = 0; hh < 4; hh++) {
                float e = av[hh] + aldh[hh];
                e = e > 0.f ? e : 0.2f * e;
                w[hh] = __expf(e);
                sv[hh] += w[hh];
            }
        }
        ssm[wi][lane] = sreg;
        *reinterpret_cast<float4*>(&wsm[wi][lane][0]) = make_float4(w[0], w[1], w[2], w[3]);
        __syncwarp();
        int cnt = min(32, end - base);
        #pragma unroll 4
        for (int j = 0; j < cnt; j++) {
            int s = ssm[wi][j];
            float wv = wsm[wi][j][hr];
            float2 hv = __half22float2(
                *reinterpret_cast<const __half2*>(&h[(size_t)s * 64 + ch]));
            acc.x = fmaf(wv, hv.x, acc.x);
            acc.y = fmaf(wv, hv.y, acc.y);
        }
        __syncwarp();
    }

    #pragma unroll
    for (int hh = 0; hh < 4; hh++)
        #pragma unroll
        for (int o = 16; o > 0; o >>= 1)
            sv[hh] += __shfl_xor_sync(0xffffffffu, sv[hh], o);

    float inv = 1.f / sv[hr];
    float vx = acc.x * inv + bias[ch];
    float vy = acc.y * inv + bias[ch + 1];
    vx = vx > 0.f ? vx : (__expf(vx) - 1.f);
    vy = vy > 0.f ? vy : (__expf(vy) - 1.f);
    if (OUT_HALF) {
        *reinterpret_cast<__half2*>(&((__half*)outv)[(size_t)gw * 64 + ch]) =
            __floats2half2_rn(vx, vy);
    } else {
        *reinterpret_cast<float2*>(&((float*)outv)[(size_t)gw * 64 + ch]) =
            make_float2(vx, vy);
    }
}

// ---------------- layer-3 aggregation: shfl-staged weights, fp16 in/out ----------------
__global__ void agg3x_kernel(const __half* __restrict__ x, const float* __restrict__ als,
                             const float* __restrict__ ald, __half* __restrict__ aggx) {
    int gw = (blockIdx.x * blockDim.x + threadIdx.x) >> 5;
    if (gw >= N_NODES) return;
    int lane = threadIdx.x & 31;
    int beg = g_offsets[gw], end = g_offsets[gw + 1];

    float aldh[6];
    #pragma unroll
    for (int q = 0; q < 3; q++) {
        float2 t = *reinterpret_cast<const float2*>(&ald[gw * 6 + 2 * q]);
        aldh[2 * q] = t.x; aldh[2 * q + 1] = t.y;
    }

    int ch = lane * 2;
    float2 acc[6];
    float sv[6];
    #pragma unroll
    for (int hh = 0; hh < 6; hh++) { acc[hh] = make_float2(0.f, 0.f); sv[hh] = 0.f; }

    for (int base = beg; base < end; base += 32) {
        int i = base + lane;
        int sreg = 0;
        float w[6];
        #pragma unroll
        for (int hh = 0; hh < 6; hh++) w[hh] = 0.f;
        if (i < end) {
            sreg = g_csr[i];
            #pragma unroll
            for (int q = 0; q < 3; q++) {
                float2 t = __ldg(reinterpret_cast<const float2*>(&als[sreg * 6 + 2 * q]));
                float e0 = t.x + aldh[2 * q];
                float e1 = t.y + aldh[2 * q + 1];
                e0 = e0 > 0.f ? e0 : 0.2f * e0;
                e1 = e1 > 0.f ? e1 : 0.2f * e1;
                w[2 * q] = __expf(e0);
                w[2 * q + 1] = __expf(e1);
            }
            #pragma unroll
            for (int hh = 0; hh < 6; hh++) sv[hh] += w[hh];
        }
        int cnt = min(32, end - base);
        for (int j = 0; j < cnt; j++) {
            int s = __shfl_sync(0xffffffffu, sreg, j);
            float w0 = __shfl_sync(0xffffffffu, w[0], j);
            float w1 = __shfl_sync(0xffffffffu, w[1], j);
            float w2 = __shfl_sync(0xffffffffu, w[2], j);
            float w3 = __shfl_sync(0xffffffffu, w[3], j);
            float w4 = __shfl_sync(0xffffffffu, w[4], j);
            float w5 = __shfl_sync(0xffffffffu, w[5], j);
            float2 hv = __half22float2(
                *reinterpret_cast<const __half2*>(&x[(size_t)s * 64 + ch]));
            acc[0].x = fmaf(w0, hv.x, acc[0].x); acc[0].y = fmaf(w0, hv.y, acc[0].y);
            acc[1].x = fmaf(w1, hv.x, acc[1].x); acc[1].y = fmaf(w1, hv.y, acc[1].y);
            acc[2].x = fmaf(w2, hv.x, acc[2].x); acc[2].y = fmaf(w2, hv.y, acc[2].y);
            acc[3].x = fmaf(w3, hv.x, acc[3].x); acc[3].y = fmaf(w3, hv.y, acc[3].y);
            acc[4].x = fmaf(w4, hv.x, acc[4].x); acc[4].y = fmaf(w4, hv.y, acc[4].y);
            acc[5].x = fmaf(w5, hv.x, acc[5].x); acc[5].y = fmaf(w5, hv.y, acc[5].y);
        }
    }

    #pragma unroll
    for (int hh = 0; hh < 6; hh++)
        #pragma unroll
        for (int o = 16; o > 0; o >>= 1)
            sv[hh] += __shfl_xor_sync(0xffffffffu, sv[hh], o);

    size_t b2 = (size_t)gw * 384;
    #pragma unroll
    for (int hh = 0; hh < 6; hh++) {
        float inv = 1.f / sv[hh];
        *reinterpret_cast<__half2*>(&aggx[b2 + hh * 64 + ch]) =
            __floats2half2_rn(acc[hh].x * inv, acc[hh].y * inv);
    }
}

// ---------------- final GEMM via tensor cores (wmma fp16 -> fp32) ----------------
// [N_PAD, 384] @ [384, 48(pad)] ; epilogue: bias + elu + log_softmax on 40 cols.
__global__ void gemm_final_wmma(const __half* __restrict__ X, const float* __restrict__ b3,
                                float* __restrict__ out, int Nn) {
    constexpr int BM = 128, FP = 48, F = 40, K = 384;
    extern __shared__ char shraw[];
    __half* Bs = reinterpret_cast<__half*>(shraw);             // 384*48 fp16 = 36864 B
    float* Cs = reinterpret_cast<float*>(shraw + K * FP * 2);  // 128*48 fp32 = 24576 B

    int tid = threadIdx.x;
    int wid = tid >> 5;

    for (int i = tid * 2; i < K * FP; i += 512)
        *reinterpret_cast<__half2*>(&Bs[i]) =
            *reinterpret_cast<const __half2*>(&g_w3h[i]);
    __syncthreads();

    int row0 = blockIdx.x * BM + wid * 16;
    wmma::fragment<wmma::accumulator, 16, 16, 16, float> c[3];
    #pragma unroll
    for (int j = 0; j < 3; j++) wmma::fill_fragment(c[j], 0.f);

    const __half* Arow = X + (size_t)row0 * K;
    #pragma unroll 4
    for (int kt = 0; kt < K / 16; kt++) {
        wmma::fragment<wmma::matrix_a, 16, 16, 16, __half, wmma::row_major> a;
        wmma::load_matrix_sync(a, Arow + kt * 16, K);
        #pragma unroll
        for (int j = 0; j < 3; j++) {
            wmma::fragment<wmma::matrix_b, 16, 16, 16, __half, wmma::row_major> b;
            wmma::load_matrix_sync(b, &Bs[(kt * 16) * FP + j * 16], FP);
            wmma::mma_sync(c[j], a, b, c[j]);
        }
    }
    #pragma unroll
    for (int j = 0; j < 3; j++)
        wmma::store_matrix_sync(&Cs[(wid * 16) * FP + j * 16], c[j], FP,
                                wmma::mem_row_major);
    __syncthreads();

    if (tid < BM) {
        int m = tid;
        int gm = blockIdx.x * BM + m;
        if (gm < Nn) {
            float v[F];
            float mxv = -1e30f;
            #pragma unroll 8
            for (int c2 = 0; c2 < F; c2++) {
                float t2 = Cs[m * FP + c2] + b3[c2];
                t2 = t2 > 0.f ? t2 : (__expf(t2) - 1.f);
                v[c2] = t2;
                mxv = fmaxf(mxv, t2);
            }
            float se = 0.f;
            #pragma unroll 8
            for (int c2 = 0; c2 < F; c2++) se += __expf(v[c2] - mxv);
            float l = __logf(se) + mxv;
            #pragma unroll 8
            for (int c2 = 0; c2 < F; c2++) out[(size_t)gm * F + c2] = v[c2] - l;
        }
    }
}

// ---------------- host launcher ----------------
extern "C" void kernel_launch(void* const* d_in, const int* in_sizes, int n_in,
                              void* d_out, int out_size) {
    const float* x   = (const float*)d_in[0];
    const void*  ei  = d_in[1];
    const float* W1  = (const float*)d_in[2];
    const float* a1s = (const float*)d_in[3];
    const float* a1d = (const float*)d_in[4];
    const float* b1  = (const float*)d_in[5];
    const float* W2  = (const float*)d_in[6];
    const float* a2s = (const float*)d_in[7];
    const float* a2d = (const float*)d_in[8];
    const float* b2  = (const float*)d_in[9];
    const float* W3  = (const float*)d_in[10];
    const float* a3s = (const float*)d_in[11];
    const float* a3d = (const float*)d_in[12];
    const float* b3  = (const float*)d_in[13];
    float* out = (float*)d_out;

    float *p_agg, *p_als, *p_ald;
    __half *p_aggx, *p_hh, *p_x2h;
    int *p_counts;
    cudaGetSymbolAddress((void**)&p_aggx, g_aggx);
    cudaGetSymbolAddress((void**)&p_agg, g_agg);
    cudaGetSymbolAddress((void**)&p_hh, g_hh);
    cudaGetSymbolAddress((void**)&p_x2h, g_x2h);
    cudaGetSymbolAddress((void**)&p_als, g_als);
    cudaGetSymbolAddress((void**)&p_ald, g_ald);
    cudaGetSymbolAddress((void**)&p_counts, g_counts);

    // ---- CSR build + layer-3 weight folding ----
    detect_idx_kernel<<<1, 32>>>((const int*)ei);
    cudaMemsetAsync(p_counts, 0, N_NODES * sizeof(int));
    prep3_kernel<<<(384 * 48 + 255) / 256, 256>>>(W3, a3s, a3d);
    count_kernel<<<(E_TOT + 255) / 256, 256>>>(ei);
    bsum_kernel<<<SCAN_NB, SCAN_B>>>();
    bscan_kernel<<<1, SCAN_B>>>();
    offsets_kernel<<<SCAN_NB, SCAN_B>>>();
    fill_kernel<<<(E_TOT + 255) / 256, 256>>>(ei);

    const int AGG_GRID = (N_NODES * 32 + 255) / 256;

    // ---- layer 1: 128 -> 4x16 concat ----
    {
        constexpr int K = 128, F = 64, BM = 128, TM = 4, TF = 8, H = 4;
        size_t smem = (size_t)(K * F + BM * (K + 1) + BM * 2 * H) * sizeof(float);
        cudaFuncSetAttribute(gemm_al_kernel<K, F, BM, TM, TF, H>,
                             cudaFuncAttributeMaxDynamicSharedMemorySize, (int)smem);
        int grid = (N_NODES + BM - 1) / BM;
        gemm_al_kernel<K, F, BM, TM, TF, H><<<grid, (BM / TM) * (F / TF), smem>>>(
            x, W1, a1s, a1d, p_hh, p_als, p_ald, N_NODES);
        agg12_kernel<false><<<AGG_GRID, 256>>>(p_hh, p_als, p_ald, b1, p_agg);
    }

    // ---- layer 2: 64 -> 4x16 concat (output fp16 for layer-3 gather) ----
    {
        constexpr int K = 64, F = 64, BM = 128, TM = 4, TF = 8, H = 4;
        size_t smem = (size_t)(K * F + BM * (K + 1) + BM * 2 * H) * sizeof(float);
        cudaFuncSetAttribute(gemm_al_kernel<K, F, BM, TM, TF, H>,
                             cudaFuncAttributeMaxDynamicSharedMemorySize, (int)smem);
        int grid = (N_NODES + BM - 1) / BM;
        gemm_al_kernel<K, F, BM, TM, TF, H><<<grid, (BM / TM) * (F / TF), smem>>>(
            p_agg, W2, a2s, a2d, p_hh, p_als, p_ald, N_NODES);
        agg12_kernel<true><<<AGG_GRID, 256>>>(p_hh, p_als, p_ald, b2, p_x2h);
    }

    // ---- layer 3: logits from x2, aggregate x2 per head, wmma GEMM + softmax ----
    logit3_kernel<<<(N_NODES + 63) / 64, 256>>>(p_x2h);
    agg3x_kernel<<<AGG_GRID, 256>>>(p_x2h, p_als, p_ald, p_aggx);
    {
        size_t smem = 384 * 48 * sizeof(__half) + 128 * 48 * sizeof(float);
        cudaFuncSetAttribute(gemm_final_wmma,
                             cudaFuncAttributeMaxDynamicSharedMemorySize, (int)smem);
        gemm_final_wmma<<<N_PAD / 128, 256, smem>>>(p_aggx, b3, out, N_NODES);
    }
}

// round 14
// speedup vs baseline: 1.5973x; 1.0569x over previous
#include <cuda_runtime.h>
#include <cuda_fp16.h>
#include <mma.h>
#include <cstdint>

using namespace nvcuda;

// ---------------- problem constants ----------------
#define N_NODES 50000
#define N_PAD   50048   // padded to multiple of 128 for wmma tiles
#define N_EDGES 1600000
#define E_TOT   (N_EDGES + N_NODES)   // + self loops
#define F_IN    128

#define SCAN_B   256
#define SCAN_NB  ((N_NODES + SCAN_B - 1) / SCAN_B)   // 196

// ---------------- device scratch ----------------
__device__ __half g_xh[(size_t)N_PAD * 128];      // input x, fp16 (pad rows stay 0)
__device__ __half g_x1h[(size_t)N_PAD * 64];      // layer-1 agg output, fp16
__device__ __half g_x2h[(size_t)N_PAD * 64];      // layer-2 agg output, fp16
__device__ __half g_hh[(size_t)N_NODES * 64];     // per-layer GEMM feature output, fp16
__device__ __half g_aggx[(size_t)N_PAD * 384];    // layer-3 per-head aggregated x, fp16
__device__ float  g_als[(size_t)N_NODES * 6];
__device__ float  g_ald[(size_t)N_NODES * 6];
__device__ __half g_w1h[128 * 64];                // W1 fp16
__device__ __half g_w2h[64 * 64];                 // W2 fp16
__device__ __half g_w3h[384 * 48];                // folded W3, fp16, padded to 48 cols
__device__ float  g_bs[64 * 6];
__device__ float  g_bd[64 * 6];
__device__ int    g_counts[N_NODES];
__device__ int    g_cursor[N_NODES];
__device__ int    g_offsets[N_NODES + 1];
__device__ int    g_csr[E_TOT];
__device__ int    g_bsum[SCAN_NB];
__device__ int    g_bpre[SCAN_NB];
__device__ int    g_idx64;

// ---------------- dtype detect ----------------
__global__ void detect_idx_kernel(const int* p) {
    int lane = threadIdx.x;
    int bad = 0;
    #pragma unroll
    for (int r = 0; r < 8; r++) {
        int i = lane + r * 32;
        if (p[2 * i + 1] != 0) bad = 1;
    }
    bad = __any_sync(0xffffffffu, bad);
    if (lane == 0) g_idx64 = bad ? 0 : 1;
}

__device__ __forceinline__ void load_edge(const void* ei, int i, int& src, int& dst) {
    if (i < N_EDGES) {
        if (g_idx64) {
            const long long* q = (const long long*)ei;
            src = (int)q[i];
            dst = (int)q[(size_t)N_EDGES + i];
        } else {
            const int* q = (const int*)ei;
            src = q[i];
            dst = q[N_EDGES + i];
        }
    } else {
        src = dst = i - N_EDGES;  // self loop
    }
}

__global__ void count_kernel(const void* ei) {
    int i = blockIdx.x * blockDim.x + threadIdx.x;
    if (i >= E_TOT) return;
    int src, dst;
    load_edge(ei, i, src, dst);
    atomicAdd(&g_counts[dst], 1);
}

// ---------------- 3-stage parallel exclusive scan ----------------
__global__ void bsum_kernel() {
    int b = blockIdx.x, t = threadIdx.x;
    int idx = b * SCAN_B + t;
    int v = (idx < N_NODES) ? g_counts[idx] : 0;
    #pragma unroll
    for (int o = 16; o > 0; o >>= 1) v += __shfl_xor_sync(0xffffffffu, v, o);
    __shared__ int ws[SCAN_B / 32];
    if ((t & 31) == 0) ws[t >> 5] = v;
    __syncthreads();
    if (t < SCAN_B / 32) {
        int s = ws[t];
        #pragma unroll
        for (int o = SCAN_B / 64; o > 0; o >>= 1) s += __shfl_xor_sync(0xffu, s, o);
        if (t == 0) g_bsum[b] = s;
    }
}

__global__ void bscan_kernel() {
    __shared__ int sm[SCAN_B];
    int t = threadIdx.x;
    int v = (t < SCAN_NB) ? g_bsum[t] : 0;
    sm[t] = v;
    __syncthreads();
    #pragma unroll
    for (int off = 1; off < SCAN_B; off <<= 1) {
        int u = (t >= off) ? sm[t - off] : 0;
        __syncthreads();
        sm[t] += u;
        __syncthreads();
    }
    if (t < SCAN_NB) g_bpre[t] = sm[t] - v;
}

__global__ void offsets_kernel() {
    __shared__ int sm[SCAN_B];
    int b = blockIdx.x, t = threadIdx.x;
    int idx = b * SCAN_B + t;
    int v = (idx < N_NODES) ? g_counts[idx] : 0;
    sm[t] = v;
    __syncthreads();
    #pragma unroll
    for (int off = 1; off < SCAN_B; off <<= 1) {
        int u = (t >= off) ? sm[t - off] : 0;
        __syncthreads();
        sm[t] += u;
        __syncthreads();
    }
    int excl = sm[t] - v + g_bpre[b];
    if (idx < N_NODES) {
        g_offsets[idx] = excl;
        g_cursor[idx] = excl;
    }
    if (idx == 0) g_offsets[N_NODES] = E_TOT;
}

__global__ void fill_kernel(const void* ei) {
    int i = blockIdx.x * blockDim.x + threadIdx.x;
    if (i >= E_TOT) return;
    int src, dst;
    load_edge(ei, i, src, dst);
    int pos = atomicAdd(&g_cursor[dst], 1);
    g_csr[pos] = src;
}

// ---------------- input/weight fp16 conversion ----------------
__global__ void convert_x_kernel(const float* __restrict__ x) {
    int i = blockIdx.x * blockDim.x + threadIdx.x;
    if (i >= N_NODES * 64) return;  // 64 half2 per row of 128
    float2 v = *reinterpret_cast<const float2*>(&x[(size_t)i * 2]);
    *reinterpret_cast<__half2*>(&g_xh[(size_t)i * 2]) = __floats2half2_rn(v.x, v.y);
}

__global__ void prep_w12_kernel(const float* __restrict__ W1, const float* __restrict__ W2) {
    int i = blockIdx.x * blockDim.x + threadIdx.x;
    if (i < 128 * 64) g_w1h[i] = __float2half(W1[i]);
    if (i < 64 * 64)  g_w2h[i] = __float2half(W2[i]);
}

// ---------------- layer-3 prep: fold attention vecs + head-mean into W3 (fp16) ----------------
__global__ void prep3_kernel(const float* __restrict__ W3, const float* __restrict__ a3s,
                             const float* __restrict__ a3d) {
    int t = blockIdx.x * blockDim.x + threadIdx.x;
    if (t < 384) {
        int k = t / 6, h = t % 6;
        float ss = 0.f, sd = 0.f;
        #pragma unroll
        for (int c = 0; c < 40; c++) {
            float w = W3[k * 240 + h * 40 + c];
            ss += w * a3s[h * 40 + c];
            sd += w * a3d[h * 40 + c];
        }
        g_bs[k * 6 + h] = ss;
        g_bd[k * 6 + h] = sd;
    }
    if (t < 384 * 48) {
        int hk = t / 48, c = t % 48;
        int h = hk >> 6, k = hk & 63;
        float v = (c < 40) ? W3[k * 240 + h * 40 + c] * (1.f / 6.f) : 0.f;
        g_w3h[t] = __float2half(v);
    }
}

// als/ald[n, 0..5] = x[n,:] @ Bs / Bd   (x is layer-2 output, fp16)
__global__ void logit3_kernel(const __half* __restrict__ X) {
    __shared__ float xs[64 * 65];
    __shared__ float Bsm[64 * 12];
    int tid = threadIdx.x;
    int n0 = blockIdx.x * 64;
    for (int i = tid; i < 768; i += 256) {
        int k = i / 12, j = i % 12;
        Bsm[k * 12 + j] = (j < 6) ? g_bs[k * 6 + j] : g_bd[k * 6 + (j - 6)];
    }
    for (int i = tid; i < 64 * 32; i += 256) {
        int m = i >> 5, k2 = (i & 31) * 2;
        int gm = n0 + m;
        float2 v = make_float2(0.f, 0.f);
        if (gm < N_NODES)
            v = __half22float2(*reinterpret_cast<const __half2*>(&X[(size_t)gm * 64 + k2]));
        xs[m * 65 + k2] = v.x;
        xs[m * 65 + k2 + 1] = v.y;
    }
    __syncthreads();
    for (int p = tid; p < 768; p += 256) {
        int m = p / 12, j = p % 12;
        float s = 0.f;
        #pragma unroll
        for (int k = 0; k < 64; k++) s = fmaf(xs[m * 65 + k], Bsm[k * 12 + j], s);
        int gm = n0 + m;
        if (gm < N_NODES) {
            if (j < 6) g_als[gm * 6 + j] = s;
            else       g_ald[gm * 6 + (j - 6)] = s;
        }
    }
}

// ---------------- wmma GEMM + logits (layers 1,2): [N,K]x[K,64] fp16->fp32 ----------------
template <int K>
__global__ void gemm_al_wmma(const __half* __restrict__ X, const __half* __restrict__ Wh,
                             const float* __restrict__ Avs, const float* __restrict__ Avd,
                             __half* __restrict__ Ho, float* __restrict__ als,
                             float* __restrict__ ald, int Nn) {
    constexpr int F = 64, BM = 128, CLD = 68;
    extern __shared__ char shraw[];
    __half* Bs = reinterpret_cast<__half*>(shraw);                   // K*64 fp16
    float* Cs = reinterpret_cast<float*>(shraw + K * F * 2);         // 128*68 fp32
    float* av = reinterpret_cast<float*>(shraw + K * F * 2 + BM * CLD * 4);  // 128

    int tid = threadIdx.x;
    int wid = tid >> 5;

    for (int i = tid * 2; i < K * F; i += 512)
        *reinterpret_cast<__half2*>(&Bs[i]) = *reinterpret_cast<const __half2*>(&Wh[i]);
    if (tid < 64) av[tid] = Avs[tid];
    else if (tid < 128) av[tid] = Avd[tid - 64];
    __syncthreads();

    int tile = blockIdx.x * BM;
    int row0 = tile + wid * 16;
    wmma::fragment<wmma::accumulator, 16, 16, 16, float> c[4];
    #pragma unroll
    for (int j = 0; j < 4; j++) wmma::fill_fragment(c[j], 0.f);

    const __half* Arow = X + (size_t)row0 * K;
    #pragma unroll
    for (int kt = 0; kt < K / 16; kt++) {
        wmma::fragment<wmma::matrix_a, 16, 16, 16, __half, wmma::row_major> a;
        wmma::load_matrix_sync(a, Arow + kt * 16, K);
        #pragma unroll
        for (int j = 0; j < 4; j++) {
            wmma::fragment<wmma::matrix_b, 16, 16, 16, __half, wmma::row_major> b;
            wmma::load_matrix_sync(b, &Bs[(kt * 16) * F + j * 16], F);
            wmma::mma_sync(c[j], a, b, c[j]);
        }
    }
    #pragma unroll
    for (int j = 0; j < 4; j++)
        wmma::store_matrix_sync(&Cs[(wid * 16) * CLD + j * 16], c[j], CLD,
                                wmma::mem_row_major);
    __syncthreads();

    // write features as fp16
    for (int i = tid; i < BM * 32; i += 256) {
        int m = i >> 5, c2 = (i & 31) * 2;
        int gm = tile + m;
        if (gm < Nn)
            *reinterpret_cast<__half2*>(&Ho[(size_t)gm * F + m * 0 + c2]) =
                __floats2half2_rn(Cs[m * CLD + c2], Cs[m * CLD + c2 + 1]);
    }
    // logits: one thread per row, 4 heads x 16 channels
    if (tid < BM) {
        int m = tid;
        int gm = tile + m;
        if (gm < Nn) {
            #pragma unroll
            for (int h = 0; h < 4; h++) {
                float ss = 0.f, sd = 0.f;
                #pragma unroll
                for (int c2 = 0; c2 < 16; c2++) {
                    float v = Cs[m * CLD + h * 16 + c2];
                    ss = fmaf(v, av[h * 16 + c2], ss);
                    sd = fmaf(v, av[64 + h * 16 + c2], sd);
                }
                als[gm * 4 + h] = ss;
                ald[gm * 4 + h] = sd;
            }
        }
    }
}

// ---------------- layers 1/2 aggregation: chunk-staged, one warp per node ----------------
__global__ void agg12_kernel(const __half* __restrict__ h, const float* __restrict__ als,
                             const float* __restrict__ ald, const float* __restrict__ bias,
                             __half* __restrict__ outh) {
    __shared__ int   ssm[8][32];
    __shared__ float wsm[8][32][4];
    int gw = (blockIdx.x * blockDim.x + threadIdx.x) >> 5;
    if (gw >= N_NODES) return;
    int lane = threadIdx.x & 31;
    int wi = (threadIdx.x >> 5) & 7;
    int beg = g_offsets[gw], end = g_offsets[gw + 1];

    float4 at = *reinterpret_cast<const float4*>(&ald[gw * 4]);
    float aldh[4] = {at.x, at.y, at.z, at.w};

    int ch = lane * 2;
    int hr = ch >> 4;  // head 0..3
    float2 acc = make_float2(0.f, 0.f);
    float sv[4] = {0.f, 0.f, 0.f, 0.f};

    for (int base = beg; base < end; base += 32) {
        int i = base + lane;
        int sreg = 0;
        float w[4] = {0.f, 0.f, 0.f, 0.f};
        if (i < end) {
            sreg = g_csr[i];
            float4 t = __ldg(reinterpret_cast<const float4*>(&als[sreg * 4]));
            float av4[4] = {t.x, t.y, t.z, t.w};
            #pragma unroll
            for (int hh = 0; hh < 4; hh++) {
                float e = av4[hh] + aldh[hh];
                e = e > 0.f ? e : 0.2f * e;
                w[hh] = __expf(e);
                sv[hh] += w[hh];
            }
        }
        ssm[wi][lane] = sreg;
        *reinterpret_cast<float4*>(&wsm[wi][lane][0]) = make_float4(w[0], w[1], w[2], w[3]);
        __syncwarp();
        int cnt = min(32, end - base);
        #pragma unroll 4
        for (int j = 0; j < cnt; j++) {
            int s = ssm[wi][j];
            float wv = wsm[wi][j][hr];
            float2 hv = __half22float2(
                *reinterpret_cast<const __half2*>(&h[(size_t)s * 64 + ch]));
            acc.x = fmaf(wv, hv.x, acc.x);
            acc.y = fmaf(wv, hv.y, acc.y);
        }
        __syncwarp();
    }

    #pragma unroll
    for (int hh = 0; hh < 4; hh++)
        #pragma unroll
        for (int o = 16; o > 0; o >>= 1)
            sv[hh] += __shfl_xor_sync(0xffffffffu, sv[hh], o);

    float inv = 1.f / sv[hr];
    float vx = acc.x * inv + bias[ch];
    float vy = acc.y * inv + bias[ch + 1];
    vx = vx > 0.f ? vx : (__expf(vx) - 1.f);
    vy = vy > 0.f ? vy : (__expf(vy) - 1.f);
    *reinterpret_cast<__half2*>(&outh[(size_t)gw * 64 + ch]) = __floats2half2_rn(vx, vy);
}

// ---------------- layer-3 aggregation: shfl-staged weights, fp16 in/out ----------------
__global__ void agg3x_kernel(const __half* __restrict__ x, const float* __restrict__ als,
                             const float* __restrict__ ald, __half* __restrict__ aggx) {
    int gw = (blockIdx.x * blockDim.x + threadIdx.x) >> 5;
    if (gw >= N_NODES) return;
    int lane = threadIdx.x & 31;
    int beg = g_offsets[gw], end = g_offsets[gw + 1];

    float aldh[6];
    #pragma unroll
    for (int q = 0; q < 3; q++) {
        float2 t = *reinterpret_cast<const float2*>(&ald[gw * 6 + 2 * q]);
        aldh[2 * q] = t.x; aldh[2 * q + 1] = t.y;
    }

    int ch = lane * 2;
    float2 acc[6];
    float sv[6];
    #pragma unroll
    for (int hh = 0; hh < 6; hh++) { acc[hh] = make_float2(0.f, 0.f); sv[hh] = 0.f; }

    for (int base = beg; base < end; base += 32) {
        int i = base + lane;
        int sreg = 0;
        float w[6];
        #pragma unroll
        for (int hh = 0; hh < 6; hh++) w[hh] = 0.f;
        if (i < end) {
            sreg = g_csr[i];
            #pragma unroll
            for (int q = 0; q < 3; q++) {
                float2 t = __ldg(reinterpret_cast<const float2*>(&als[sreg * 6 + 2 * q]));
                float e0 = t.x + aldh[2 * q];
                float e1 = t.y + aldh[2 * q + 1];
                e0 = e0 > 0.f ? e0 : 0.2f * e0;
                e1 = e1 > 0.f ? e1 : 0.2f * e1;
                w[2 * q] = __expf(e0);
                w[2 * q + 1] = __expf(e1);
            }
            #pragma unroll
            for (int hh = 0; hh < 6; hh++) sv[hh] += w[hh];
        }
        int cnt = min(32, end - base);
        for (int j = 0; j < cnt; j++) {
            int s = __shfl_sync(0xffffffffu, sreg, j);
            float w0 = __shfl_sync(0xffffffffu, w[0], j);
            float w1 = __shfl_sync(0xffffffffu, w[1], j);
            float w2 = __shfl_sync(0xffffffffu, w[2], j);
            float w3 = __shfl_sync(0xffffffffu, w[3], j);
            float w4 = __shfl_sync(0xffffffffu, w[4], j);
            float w5 = __shfl_sync(0xffffffffu, w[5], j);
            float2 hv = __half22float2(
                *reinterpret_cast<const __half2*>(&x[(size_t)s * 64 + ch]));
            acc[0].x = fmaf(w0, hv.x, acc[0].x); acc[0].y = fmaf(w0, hv.y, acc[0].y);
            acc[1].x = fmaf(w1, hv.x, acc[1].x); acc[1].y = fmaf(w1, hv.y, acc[1].y);
            acc[2].x = fmaf(w2, hv.x, acc[2].x); acc[2].y = fmaf(w2, hv.y, acc[2].y);
            acc[3].x = fmaf(w3, hv.x, acc[3].x); acc[3].y = fmaf(w3, hv.y, acc[3].y);
            acc[4].x = fmaf(w4, hv.x, acc[4].x); acc[4].y = fmaf(w4, hv.y, acc[4].y);
            acc[5].x = fmaf(w5, hv.x, acc[5].x); acc[5].y = fmaf(w5, hv.y, acc[5].y);
        }
    }

    #pragma unroll
    for (int hh = 0; hh < 6; hh++)
        #pragma unroll
        for (int o = 16; o > 0; o >>= 1)
            sv[hh] += __shfl_xor_sync(0xffffffffu, sv[hh], o);

    size_t b2 = (size_t)gw * 384;
    #pragma unroll
    for (int hh = 0; hh < 6; hh++) {
        float inv = 1.f / sv[hh];
        *reinterpret_cast<__half2*>(&aggx[b2 + hh * 64 + ch]) =
            __floats2half2_rn(acc[hh].x * inv, acc[hh].y * inv);
    }
}

// ---------------- final GEMM via tensor cores (wmma fp16 -> fp32) ----------------
__global__ void gemm_final_wmma(const __half* __restrict__ X, const float* __restrict__ b3,
                                float* __restrict__ out, int Nn) {
    constexpr int BM = 128, FP = 48, F = 40, K = 384;
    extern __shared__ char shraw[];
    __half* Bs = reinterpret_cast<__half*>(shraw);             // 384*48 fp16
    float* Cs = reinterpret_cast<float*>(shraw + K * FP * 2);  // 128*48 fp32

    int tid = threadIdx.x;
    int wid = tid >> 5;

    for (int i = tid * 2; i < K * FP; i += 512)
        *reinterpret_cast<__half2*>(&Bs[i]) =
            *reinterpret_cast<const __half2*>(&g_w3h[i]);
    __syncthreads();

    int row0 = blockIdx.x * BM + wid * 16;
    wmma::fragment<wmma::accumulator, 16, 16, 16, float> c[3];
    #pragma unroll
    for (int j = 0; j < 3; j++) wmma::fill_fragment(c[j], 0.f);

    const __half* Arow = X + (size_t)row0 * K;
    #pragma unroll 4
    for (int kt = 0; kt < K / 16; kt++) {
        wmma::fragment<wmma::matrix_a, 16, 16, 16, __half, wmma::row_major> a;
        wmma::load_matrix_sync(a, Arow + kt * 16, K);
        #pragma unroll
        for (int j = 0; j < 3; j++) {
            wmma::fragment<wmma::matrix_b, 16, 16, 16, __half, wmma::row_major> b;
            wmma::load_matrix_sync(b, &Bs[(kt * 16) * FP + j * 16], FP);
            wmma::mma_sync(c[j], a, b, c[j]);
        }
    }
    #pragma unroll
    for (int j = 0; j < 3; j++)
        wmma::store_matrix_sync(&Cs[(wid * 16) * FP + j * 16], c[j], FP,
                                wmma::mem_row_major);
    __syncthreads();

    if (tid < BM) {
        int m = tid;
        int gm = blockIdx.x * BM + m;
        if (gm < Nn) {
            float v[F];
            float mxv = -1e30f;
            #pragma unroll 8
            for (int c2 = 0; c2 < F; c2++) {
                float t2 = Cs[m * FP + c2] + b3[c2];
                t2 = t2 > 0.f ? t2 : (__expf(t2) - 1.f);
                v[c2] = t2;
                mxv = fmaxf(mxv, t2);
            }
            float se = 0.f;
            #pragma unroll 8
            for (int c2 = 0; c2 < F; c2++) se += __expf(v[c2] - mxv);
            float l = __logf(se) + mxv;
            #pragma unroll 8
            for (int c2 = 0; c2 < F; c2++) out[(size_t)gm * F + c2] = v[c2] - l;
        }
    }
}

// ---------------- host launcher ----------------
extern "C" void kernel_launch(void* const* d_in, const int* in_sizes, int n_in,
                              void* d_out, int out_size) {
    const float* x   = (const float*)d_in[0];
    const void*  ei  = d_in[1];
    const float* W1  = (const float*)d_in[2];
    const float* a1s = (const float*)d_in[3];
    const float* a1d = (const float*)d_in[4];
    const float* b1  = (const float*)d_in[5];
    const float* W2  = (const float*)d_in[6];
    const float* a2s = (const float*)d_in[7];
    const float* a2d = (const float*)d_in[8];
    const float* b2  = (const float*)d_in[9];
    const float* W3  = (const float*)d_in[10];
    const float* a3s = (const float*)d_in[11];
    const float* a3d = (const float*)d_in[12];
    const float* b3  = (const float*)d_in[13];
    float* out = (float*)d_out;

    float *p_als, *p_ald;
    __half *p_aggx, *p_hh, *p_xh, *p_x1h, *p_x2h, *p_w1h, *p_w2h;
    int *p_counts;
    cudaGetSymbolAddress((void**)&p_aggx, g_aggx);
    cudaGetSymbolAddress((void**)&p_hh, g_hh);
    cudaGetSymbolAddress((void**)&p_xh, g_xh);
    cudaGetSymbolAddress((void**)&p_x1h, g_x1h);
    cudaGetSymbolAddress((void**)&p_x2h, g_x2h);
    cudaGetSymbolAddress((void**)&p_w1h, g_w1h);
    cudaGetSymbolAddress((void**)&p_w2h, g_w2h);
    cudaGetSymbolAddress((void**)&p_als, g_als);
    cudaGetSymbolAddress((void**)&p_ald, g_ald);
    cudaGetSymbolAddress((void**)&p_counts, g_counts);

    // ---- CSR build + conversions + weight folding ----
    detect_idx_kernel<<<1, 32>>>((const int*)ei);
    cudaMemsetAsync(p_counts, 0, N_NODES * sizeof(int));
    convert_x_kernel<<<(N_NODES * 64 + 255) / 256, 256>>>(x);
    prep_w12_kernel<<<(128 * 64 + 255) / 256, 256>>>(W1, W2);
    prep3_kernel<<<(384 * 48 + 255) / 256, 256>>>(W3, a3s, a3d);
    count_kernel<<<(E_TOT + 255) / 256, 256>>>(ei);
    bsum_kernel<<<SCAN_NB, SCAN_B>>>();
    bscan_kernel<<<1, SCAN_B>>>();
    offsets_kernel<<<SCAN_NB, SCAN_B>>>();
    fill_kernel<<<(E_TOT + 255) / 256, 256>>>(ei);

    const int AGG_GRID = (N_NODES * 32 + 255) / 256;
    const int GEMM_GRID = N_PAD / 128;

    // ---- layer 1: 128 -> 4x16 concat (wmma) ----
    {
        size_t smem = 128 * 64 * 2 + 128 * 68 * 4 + 128 * 4;
        cudaFuncSetAttribute(gemm_al_wmma<128>,
                             cudaFuncAttributeMaxDynamicSharedMemorySize, (int)smem);
        gemm_al_wmma<128><<<GEMM_GRID, 256, smem>>>(
            p_xh, p_w1h, a1s, a1d, p_hh, p_als, p_ald, N_NODES);
        agg12_kernel<<<AGG_GRID, 256>>>(p_hh, p_als, p_ald, b1, p_x1h);
    }

    // ---- layer 2: 64 -> 4x16 concat (wmma) ----
    {
        size_t smem = 64 * 64 * 2 + 128 * 68 * 4 + 128 * 4;
        cudaFuncSetAttribute(gemm_al_wmma<64>,
                             cudaFuncAttributeMaxDynamicSharedMemorySize, (int)smem);
        gemm_al_wmma<64><<<GEMM_GRID, 256, smem>>>(
            p_x1h, p_w2h, a2s, a2d, p_hh, p_als, p_ald, N_NODES);
        agg12_kernel<<<AGG_GRID, 256>>>(p_hh, p_als, p_ald, b2, p_x2h);
    }

    // ---- layer 3: logits from x2, aggregate x2 per head, wmma GEMM + softmax ----
    logit3_kernel<<<(N_NODES + 63) / 64, 256>>>(p_x2h);
    agg3x_kernel<<<AGG_GRID, 256>>>(p_x2h, p_als, p_ald, p_aggx);
    {
        size_t smem = 384 * 48 * sizeof(__half) + 128 * 48 * sizeof(float);
        cudaFuncSetAttribute(gemm_final_wmma,
                             cudaFuncAttributeMaxDynamicSharedMemorySize, (int)smem);
        gemm_final_wmma<<<N_PAD / 128, 256, smem>>>(p_aggx, b3, out, N_NODES);
    }
}